// round 14
// baseline (speedup 1.0000x reference)
#include <cuda_runtime.h>
#include <cuda.h>
#include <cuda_bf16.h>
#include <cuda_fp16.h>
#include <cstdint>

#if defined(__CUDA_ARCH_FEAT_SM103_ALL) || defined(__CUDA_ARCH_FEAT_SM100_ALL) || \
    (defined(__CUDA_ARCH_SPECIFIC__) && (__CUDA_ARCH_SPECIFIC__ >= 1000))
#define HAS_TCGEN05 1
#else
#define HAS_TCGEN05 0
#endif

#define Bb 2
#define Ss 2304
#define Hh 24
#define HD 128
#define DM 3072
#define N3 9216
#define KD 3072
#define MR (Bb*Ss)

__device__ alignas(128) __nv_bfloat16 g_Ah[(size_t)MR * KD];
__device__ alignas(128) __nv_bfloat16 g_Al[(size_t)MR * KD];
__device__ alignas(128) __nv_bfloat16 g_Wh[(size_t)N3 * KD];
__device__ alignas(128) __nv_bfloat16 g_Wl[(size_t)N3 * KD];
#define NBH ((size_t)Bb * Hh * Ss * HD)
__device__ alignas(128) __nv_bfloat16 g_qh[NBH];
__device__ alignas(128) __nv_bfloat16 g_ql[NBH];
__device__ alignas(128) __nv_bfloat16 g_kh[NBH];
__device__ alignas(128) __nv_bfloat16 g_kl[NBH];
__device__ alignas(128) __half g_vh[NBH];
__device__ alignas(128) __half g_vt[NBH];

__device__ __forceinline__ uint32_t smem_u32(const void* p) {
    uint32_t a;
    asm("{ .reg .u64 t; cvta.to.shared.u64 t, %1; cvt.u32.u64 %0, t; }" : "=r"(a) : "l"(p));
    return a;
}
__device__ __forceinline__ uint32_t h2_as_u32(__half2 h) {
    uint32_t u;
    asm("mov.b32 %0, %1;" : "=r"(u) : "r"(*(uint32_t*)&h));
    return u;
}
#define MK_DESC(addr) ((uint64_t(2) << 61) | (uint64_t(1) << 46) | (uint64_t(64) << 32) | \
                       (uint64_t(1) << 16) | ((uint64_t)((addr) >> 4) & 0x3FFF))
#define MBAR_INIT(m, c) asm volatile("mbarrier.init.shared.b64 [%0], %1;" :: "r"(m), "r"(c) : "memory")
#define MBAR_WAIT(m, p) asm volatile( \
    "{\n\t.reg .pred P1;\n\t" \
    "WL%=:\n\tmbarrier.try_wait.parity.acquire.cta.shared::cta.b64 P1, [%0], %1, 0x989680;\n\t" \
    "@P1 bra.uni WD%=;\n\tbra.uni WL%=;\n\tWD%=:\n\t}" \
    :: "r"(m), "r"(p) : "memory")
#define MBAR_EXPECT_TX(m, n) asm volatile( \
    "mbarrier.arrive.expect_tx.shared.b64 _, [%0], %1;" :: "r"(m), "r"(n) : "memory")
#define TMA_3D(dst, map, x, y, z, mb) asm volatile( \
    "cp.async.bulk.tensor.3d.shared::cta.global.tile.mbarrier::complete_tx::bytes " \
    "[%0], [%1, {%2, %3, %4}], [%5];" \
    :: "r"(dst), "l"(map), "r"(x), "r"(y), "r"(z), "r"(mb) : "memory")
#define TMA_2D_CG2(dst, map, x, y, mb) asm volatile( \
    "{\n\t.reg .b32 lb;\n\tand.b32 lb, %4, 0xFEFFFFFF;\n\t" \
    "cp.async.bulk.tensor.2d.cta_group::2.shared::cluster.global.tile." \
    "mbarrier::complete_tx::bytes [%0], [%1, {%2, %3}], [lb];\n\t}" \
    :: "r"(dst), "l"(map), "r"(x), "r"(y), "r"(mb) : "memory")
#define CLUSTER_SYNC() do { \
    asm volatile("barrier.cluster.arrive.aligned;" ::: "memory"); \
    asm volatile("barrier.cluster.wait.aligned;" ::: "memory"); } while (0)

#if HAS_TCGEN05
__device__ __forceinline__ void mma_ss_cg2(uint32_t d, uint64_t a, uint64_t b,
                                           uint32_t idesc, uint32_t en) {
    asm volatile(
        "{\n\t.reg .pred p;\n\tsetp.ne.u32 p, %4, 0;\n\t"
        "tcgen05.mma.cta_group::2.kind::f16 [%0], %1, %2, %3, "
        "{%5, %5, %5, %5, %5, %5, %5, %5}, p;\n\t}"
        :: "r"(d), "l"(a), "l"(b), "r"(idesc), "r"(en), "r"(0u) : "memory");
}
__device__ __forceinline__ void mma_ts(uint32_t d, uint32_t a, uint64_t b,
                                       uint32_t idesc, uint32_t en) {
    asm volatile(
        "{\n\t.reg .pred p;\n\tsetp.ne.u32 p, %4, 0;\n\t"
        "tcgen05.mma.cta_group::1.kind::f16 [%0], [%1], %2, %3, {%5, %5, %5, %5}, p;\n\t}"
        :: "r"(d), "r"(a), "l"(b), "r"(idesc), "r"(en), "r"(0u) : "memory");
}
#define TC_COMMIT(m) asm volatile( \
    "tcgen05.commit.cta_group::1.mbarrier::arrive::one.shared::cluster.b64 [%0];" :: "r"(m) : "memory")
#define TC_COMMIT_MC2(m) asm volatile( \
    "tcgen05.commit.cta_group::2.mbarrier::arrive::one.shared::cluster.multicast::cluster.b64 [%0], %1;" \
    :: "r"(m), "h"((uint16_t)0x3) : "memory")
#define TC_ALLOC(sm, n)  asm volatile("tcgen05.alloc.cta_group::1.sync.aligned.shared::cta.b32 [%0], %1;" :: "r"(sm), "r"(n) : "memory")
#define TC_DEALLOC(t, n) asm volatile("tcgen05.dealloc.cta_group::1.sync.aligned.b32 %0, %1;" :: "r"(t), "r"(n))
#define TC_ALLOC_CG2(sm, n)  asm volatile("tcgen05.alloc.cta_group::2.sync.aligned.shared::cta.b32 [%0], %1;" :: "r"(sm), "r"(n) : "memory")
#define TC_DEALLOC_CG2(t, n) asm volatile("tcgen05.dealloc.cta_group::2.sync.aligned.b32 %0, %1;" :: "r"(t), "r"(n))
#define TC_RELINQ_CG2() asm volatile("tcgen05.relinquish_alloc_permit.cta_group::2.sync.aligned;")
#define TC_FENCE_AFTER() asm volatile("tcgen05.fence::after_thread_sync;" ::: "memory")
#define TC_FENCE_BEFORE() asm volatile("tcgen05.fence::before_thread_sync;" ::: "memory")
#define TC_WAIT_LD()     asm volatile("tcgen05.wait::ld.sync.aligned;" ::: "memory")
#define TC_WAIT_ST()     asm volatile("tcgen05.wait::st.sync.aligned;" ::: "memory")
#define FENCE_ASYNC()    asm volatile("fence.proxy.async.shared::cta;" ::: "memory")

#define TC_LD_X32(r, a) asm volatile( \
    "tcgen05.ld.sync.aligned.32x32b.x32.b32 " \
    "{%0, %1, %2, %3, %4, %5, %6, %7, %8, %9, %10, %11, %12, %13, %14, %15, " \
    "%16, %17, %18, %19, %20, %21, %22, %23, %24, %25, %26, %27, %28, %29, %30, %31}, [%32];" \
    : "=r"((r)[0]), "=r"((r)[1]), "=r"((r)[2]), "=r"((r)[3]), "=r"((r)[4]), "=r"((r)[5]), \
      "=r"((r)[6]), "=r"((r)[7]), "=r"((r)[8]), "=r"((r)[9]), "=r"((r)[10]), "=r"((r)[11]), \
      "=r"((r)[12]), "=r"((r)[13]), "=r"((r)[14]), "=r"((r)[15]), "=r"((r)[16]), "=r"((r)[17]), \
      "=r"((r)[18]), "=r"((r)[19]), "=r"((r)[20]), "=r"((r)[21]), "=r"((r)[22]), "=r"((r)[23]), \
      "=r"((r)[24]), "=r"((r)[25]), "=r"((r)[26]), "=r"((r)[27]), "=r"((r)[28]), "=r"((r)[29]), \
      "=r"((r)[30]), "=r"((r)[31]) : "r"(a))

#define TC_ST_X32(a, r) asm volatile( \
    "tcgen05.st.sync.aligned.32x32b.x32.b32 [%0], " \
    "{%1, %2, %3, %4, %5, %6, %7, %8, %9, %10, %11, %12, %13, %14, %15, %16, " \
    "%17, %18, %19, %20, %21, %22, %23, %24, %25, %26, %27, %28, %29, %30, %31, %32};" \
    :: "r"(a), \
       "r"((r)[0]), "r"((r)[1]), "r"((r)[2]), "r"((r)[3]), "r"((r)[4]), "r"((r)[5]), \
       "r"((r)[6]), "r"((r)[7]), "r"((r)[8]), "r"((r)[9]), "r"((r)[10]), "r"((r)[11]), \
       "r"((r)[12]), "r"((r)[13]), "r"((r)[14]), "r"((r)[15]), "r"((r)[16]), "r"((r)[17]), \
       "r"((r)[18]), "r"((r)[19]), "r"((r)[20]), "r"((r)[21]), "r"((r)[22]), "r"((r)[23]), \
       "r"((r)[24]), "r"((r)[25]), "r"((r)[26]), "r"((r)[27]), "r"((r)[28]), "r"((r)[29]), \
       "r"((r)[30]), "r"((r)[31]) : "memory")
#endif

// ---- Kernel 0: fused fp32 -> (hi,lo) bf16 ----
__global__ __launch_bounds__(256) void cvt_split2(const float* __restrict__ a,
                                                  const float* __restrict__ w,
                                                  __nv_bfloat16* __restrict__ ah,
                                                  __nv_bfloat16* __restrict__ al,
                                                  __nv_bfloat16* __restrict__ wh,
                                                  __nv_bfloat16* __restrict__ wl,
                                                  int na4, int ntot) {
    int i = blockIdx.x * 256 + threadIdx.x;
    if (i >= ntot) return;
    const float* x; __nv_bfloat16 *hi, *lo; int j;
    if (i < na4) { x = a; hi = ah; lo = al; j = i; }
    else         { x = w; hi = wh; lo = wl; j = i - na4; }
    float4 v = ((const float4*)x)[j];
    __nv_bfloat16 h0 = __float2bfloat16(v.x), h1 = __float2bfloat16(v.y);
    __nv_bfloat16 h2 = __float2bfloat16(v.z), h3 = __float2bfloat16(v.w);
    __nv_bfloat16 l0 = __float2bfloat16(v.x - __bfloat162float(h0));
    __nv_bfloat16 l1 = __float2bfloat16(v.y - __bfloat162float(h1));
    __nv_bfloat16 l2 = __float2bfloat16(v.z - __bfloat162float(h2));
    __nv_bfloat16 l3 = __float2bfloat16(v.w - __bfloat162float(h3));
    ((__nv_bfloat162*)hi)[2 * j] = __nv_bfloat162(h0, h1);
    ((__nv_bfloat162*)hi)[2 * j + 1] = __nv_bfloat162(h2, h3);
    ((__nv_bfloat162*)lo)[2 * j] = __nv_bfloat162(l0, l1);
    ((__nv_bfloat162*)lo)[2 * j + 1] = __nv_bfloat162(l2, l3);
}

// ---- Kernel 1: cg2 GEMM, 256x512 pair tile, fused epilogue (unchanged R13) ----
#define GS_AH 0
#define GS_AL 16384
#define GS_W0H 32768
#define GS_W0L 49152
#define GS_W1H 65536
#define GS_W1L 81920
#define G_STG 98304
#define SM_BIAS  196608
#define SM_TMEMP 198656
#define SM_MB    198664
#define SM_KF    198680
#define GEMM_SMEM 198784
#define IDESC_CG2N256 0x10400490u
#define IDESC_BF16 0x8200490u
#define IDESC_FP16 0x8200010u
#define NCH 48

extern __shared__ float smf[];

__global__ __launch_bounds__(256) __cluster_dims__(2, 1, 1)
void qkv_gemm_tc(const float* __restrict__ bias,
                 const float* __restrict__ wq, const float* __restrict__ wk,
                 const float* __restrict__ cs, const float* __restrict__ sn,
                 const int* __restrict__ tsl,
                 const __grid_constant__ CUtensorMap mAh,
                 const __grid_constant__ CUtensorMap mAl,
                 const __grid_constant__ CUtensorMap mWh,
                 const __grid_constant__ CUtensorMap mWl) {
#if HAS_TCGEN05
    char* sm = (char*)smf;
    uint32_t sb = smem_u32(sm);
    int t = threadIdx.x;
    int wid = t >> 5;
    int rank = blockIdx.x & 1;
    int m0 = (blockIdx.x >> 1) * 256 + rank * 128;
    int n0 = blockIdx.y * 512;

    if (wid == 0) TC_ALLOC_CG2(sb + SM_TMEMP, 512);
    if (t == 0) {
        MBAR_INIT(sb + SM_MB + 0, 1);
        MBAR_INIT(sb + SM_MB + 8, 1);
        MBAR_INIT(sb + SM_KF + 0, 1);
        MBAR_INIT(sb + SM_KF + 8, 1);
        FENCE_ASYNC();
        if (rank == 0) {
            MBAR_EXPECT_TX(sb + SM_KF + 0, 196608u);
            MBAR_EXPECT_TX(sb + SM_KF + 8, 196608u);
        }
    }
    ((float*)(sm + SM_BIAS))[t] = bias[n0 + t];
    ((float*)(sm + SM_BIAS))[t + 256] = bias[n0 + t + 256];
    __syncthreads();
    CLUSTER_SYNC();
    uint32_t tmem;
    asm volatile("ld.shared.b32 %0, [%1];" : "=r"(tmem) : "r"(sb + SM_TMEMP));

    if (t == 0) {
#pragma unroll
        for (int c = 0; c < 2; c++) {
            uint32_t stg = sb + c * G_STG, kfb = sb + SM_KF + c * 8;
            int k0 = c * 64;
            TMA_2D_CG2(stg + GS_AH,  &mAh, k0, m0, kfb);
            TMA_2D_CG2(stg + GS_AL,  &mAl, k0, m0, kfb);
            TMA_2D_CG2(stg + GS_W0H, &mWh, k0, n0 + rank * 128, kfb);
            TMA_2D_CG2(stg + GS_W0L, &mWl, k0, n0 + rank * 128, kfb);
            TMA_2D_CG2(stg + GS_W1H, &mWh, k0, n0 + 256 + rank * 128, kfb);
            TMA_2D_CG2(stg + GS_W1L, &mWl, k0, n0 + 256 + rank * 128, kfb);
        }
        const int ca[3] = {0, 0, 1}, cw[3] = {0, 1, 0};
        for (int i = 0; i < NCH; i++) {
            int s = i & 1;
            if (rank == 0) {
                MBAR_WAIT(sb + SM_KF + s * 8, (i >> 1) & 1);
                if (i + 2 < NCH) MBAR_EXPECT_TX(sb + SM_KF + s * 8, 196608u);
                uint32_t stg = sb + s * G_STG;
                uint64_t dA[2]  = {MK_DESC(stg + GS_AH), MK_DESC(stg + GS_AL)};
                uint64_t dW0[2] = {MK_DESC(stg + GS_W0H), MK_DESC(stg + GS_W0L)};
                uint64_t dW1[2] = {MK_DESC(stg + GS_W1H), MK_DESC(stg + GS_W1L)};
#pragma unroll
                for (int c3 = 0; c3 < 3; c3++) {
                    uint64_t b0 = cw[c3] ? dW0[1] : dW0[0];
                    uint64_t b1 = cw[c3] ? dW1[1] : dW1[0];
                    uint64_t aa = dA[ca[c3]];
#pragma unroll
                    for (int ks = 0; ks < 4; ks++) {
                        uint32_t en = (i | c3 | ks) ? 1u : 0u;
                        mma_ss_cg2(tmem,       aa + ks * 2, b0 + ks * 2, IDESC_CG2N256, en);
                        mma_ss_cg2(tmem + 256, aa + ks * 2, b1 + ks * 2, IDESC_CG2N256, en);
                    }
                }
                TC_COMMIT_MC2(sb + SM_MB + s * 8);
            }
            if (i >= 1 && i + 1 < NCH) {
                int s2 = (i + 1) & 1;
                MBAR_WAIT(sb + SM_MB + s2 * 8, ((i - 1) >> 1) & 1);
                uint32_t stg = sb + s2 * G_STG, kfb = sb + SM_KF + s2 * 8;
                int k0 = (i + 1) * 64;
                TMA_2D_CG2(stg + GS_AH,  &mAh, k0, m0, kfb);
                TMA_2D_CG2(stg + GS_AL,  &mAl, k0, m0, kfb);
                TMA_2D_CG2(stg + GS_W0H, &mWh, k0, n0 + rank * 128, kfb);
                TMA_2D_CG2(stg + GS_W0L, &mWl, k0, n0 + rank * 128, kfb);
                TMA_2D_CG2(stg + GS_W1H, &mWh, k0, n0 + 256 + rank * 128, kfb);
                TMA_2D_CG2(stg + GS_W1L, &mWl, k0, n0 + 256 + rank * 128, kfb);
            }
        }
        MBAR_WAIT(sb + SM_MB + 0, 1);
        MBAR_WAIT(sb + SM_MB + 8, 1);
    }
    __syncthreads();
    TC_FENCE_AFTER();

    {
        int r = t & 127;
        int m = m0 + r;
        int b = m / Ss, s2 = m % Ss;
        int sec = n0 / DM;
        int h0 = (n0 % DM) / HD;
        uint32_t tw = tmem + ((uint32_t)(wid & 3) << 21);
        int T = tsl[0];
        bool rope = (s2 >= T);
        int p = s2 - T;
#pragma unroll
        for (int hc2 = 0; hc2 < 2; hc2++) {
            int hc = (t >> 7) + hc2 * 2;
            uint32_t cbase = tw + hc * 128;
            const float* bs = (const float*)(sm + SM_BIAS) + hc * 128;
            size_t obase = ((size_t)(b * Hh + h0 + hc) * Ss + s2) * (size_t)HD;

            if (sec == 2) {
                __half* dv = g_vh + obase;
#pragma unroll
                for (int cb = 0; cb < 4; cb++) {
                    uint32_t rg[32];
                    TC_LD_X32(rg, cbase + cb * 32);
                    TC_WAIT_LD();
                    __half hb[32];
#pragma unroll
                    for (int j = 0; j < 32; j += 2) {
                        float a0 = __uint_as_float(rg[j]) + bs[cb * 32 + j];
                        float a1 = __uint_as_float(rg[j + 1]) + bs[cb * 32 + j + 1];
                        *(__half2*)(hb + j) = __float22half2_rn(make_float2(a0, a1));
                    }
#pragma unroll
                    for (int q4 = 0; q4 < 4; q4++)
                        *(uint4*)(dv + cb * 32 + q4 * 8) = *(uint4*)(hb + q4 * 8);
                }
            } else {
                const float* wn = (sec == 0) ? wq : wk;
                float ssq = 0.0f;
#pragma unroll
                for (int cb = 0; cb < 4; cb++) {
                    uint32_t rg[32];
                    TC_LD_X32(rg, cbase + cb * 32);
                    TC_WAIT_LD();
#pragma unroll
                    for (int j = 0; j < 32; j++) {
                        float a = __uint_as_float(rg[j]) + bs[cb * 32 + j];
                        ssq += a * a;
                    }
                }
                float rms = rsqrtf(ssq * (1.0f / 128.0f) + 1e-6f);
                float qscale = (sec == 0) ? 0.08838834764831845f : 1.0f;
                __nv_bfloat16* dh = ((sec == 0) ? g_qh : g_kh) + obase;
                __nv_bfloat16* dl = ((sec == 0) ? g_ql : g_kl) + obase;
#pragma unroll
                for (int cb = 0; cb < 4; cb++) {
                    uint32_t rg[32];
                    TC_LD_X32(rg, cbase + cb * 32);
                    TC_WAIT_LD();
                    float y[32];
#pragma unroll
                    for (int j = 0; j < 32; j++)
                        y[j] = (__uint_as_float(rg[j]) + bs[cb * 32 + j]) * rms * wn[cb * 32 + j];
                    if (rope) {
#pragma unroll
                        for (int jj = 0; jj < 16; jj++) {
                            float c = cs[p * 64 + cb * 16 + jj], sv = sn[p * 64 + cb * 16 + jj];
                            float x1 = y[2 * jj], x2 = y[2 * jj + 1];
                            y[2 * jj] = x1 * c - x2 * sv;
                            y[2 * jj + 1] = x2 * c + x1 * sv;
                        }
                    }
                    __nv_bfloat16 hb[32], lb[32];
#pragma unroll
                    for (int j = 0; j < 32; j++) {
                        float v = y[j] * qscale;
                        __nv_bfloat16 hv = __float2bfloat16(v);
                        hb[j] = hv;
                        lb[j] = __float2bfloat16(v - __bfloat162float(hv));
                    }
#pragma unroll
                    for (int q4 = 0; q4 < 4; q4++) {
                        *(uint4*)(dh + cb * 32 + q4 * 8) = *(uint4*)(hb + q4 * 8);
                        *(uint4*)(dl + cb * 32 + q4 * 8) = *(uint4*)(lb + q4 * 8);
                    }
                }
            }
        }
    }
    __syncthreads();
    if (wid == 0) { TC_RELINQ_CG2(); TC_DEALLOC_CG2(tmem, 512); }
    CLUSTER_SYNC();
#endif
}

// ---- Kernel 2b: V transpose ----
__global__ __launch_bounds__(256) void v_transpose() {
    __shared__ __half ts[128 * 129];
    int t = threadIdx.x;
    int s0 = blockIdx.x * 128;
    int bh = blockIdx.y;
    const __half* src = g_vh + ((size_t)bh * Ss + s0) * HD;
#pragma unroll
    for (int i = 0; i < 8; i++) {
        int idx = t + i * 256;
        int s = idx >> 4, c8 = idx & 15;
        uint4 v = *(const uint4*)(src + s * HD + c8 * 8);
        __half tmp[8];
        *(uint4*)tmp = v;
#pragma unroll
        for (int j = 0; j < 8; j++) ts[s * 129 + c8 * 8 + j] = tmp[j];
    }
    __syncthreads();
    __half* dst = g_vt + (size_t)bh * HD * Ss;
#pragma unroll
    for (int i = 0; i < 8; i++) {
        int idx = t + i * 256;
        int d = idx >> 4, s8 = idx & 15;
        __half o[8];
#pragma unroll
        for (int j = 0; j < 8; j++) o[j] = ts[(s8 * 8 + j) * 129 + d];
        *(uint4*)(dst + (size_t)d * Ss + s0 + s8 * 8) = *(uint4*)o;
    }
}

// ---- Kernel 3: attention — warp-specialized (warp 8 = control) ----
#define A_STG 98304
#define AS_KH 0
#define AS_KL 32768
#define AS_V  65536
#define A_SMAX 196608
#define A_SSUM 197632
#define A_PTR  198656
#define A_MBS  198664   // mbS[2]
#define A_MBO  198680
#define A_KF   198688   // kf[2]
#define ATT_SMEM 198784
#define NT 18
// TMEM: O[0:128) S0[128:256) S1[256:384) QH[384:448) QL[448:512); P aliases S cols 0-63
#define TO_O  0
#define TO_QH 384
#define TO_QL 448

__device__ __forceinline__ uint32_t dstep(int ks) {
    return (uint32_t)((ks >> 2) * 1024 + (ks & 3) * 2);
}

#if HAS_TCGEN05
__device__ __forceinline__ void attn_tma6(uint32_t sb, int tile, int bh,
                                          const CUtensorMap* mKh, const CUtensorMap* mKl,
                                          const CUtensorMap* mVt) {
    int s2 = tile & 1;
    uint32_t st2 = sb + s2 * A_STG;
    int kt = tile * 128;
    MBAR_EXPECT_TX(sb + A_KF + s2 * 8, 98304u);
    TMA_3D(st2 + AS_KH,         mKh, 0,  kt, bh, sb + A_KF + s2 * 8);
    TMA_3D(st2 + AS_KH + 16384, mKh, 64, kt, bh, sb + A_KF + s2 * 8);
    TMA_3D(st2 + AS_KL,         mKl, 0,  kt, bh, sb + A_KF + s2 * 8);
    TMA_3D(st2 + AS_KL + 16384, mKl, 64, kt, bh, sb + A_KF + s2 * 8);
    TMA_3D(st2 + AS_V,          mVt, kt,      0, bh, sb + A_KF + s2 * 8);
    TMA_3D(st2 + AS_V + 16384,  mVt, kt + 64, 0, bh, sb + A_KF + s2 * 8);
}
// wait kf(tile), issue S-MMA(tile), commit mbS[tile&1]
__device__ __forceinline__ void attn_smma(uint32_t tmem, uint32_t sb, int tile) {
    int s = tile & 1;
    uint32_t stg = sb + s * A_STG;
    uint32_t to_s = 128 + (uint32_t)s * 128;
    MBAR_WAIT(sb + A_KF + s * 8, (tile >> 1) & 1);
    uint64_t dKh = MK_DESC(stg + AS_KH);
    uint64_t dKl = MK_DESC(stg + AS_KL);
#pragma unroll
    for (int ks = 0; ks < 8; ks++)
        mma_ts(tmem + to_s, tmem + TO_QH + ks * 8, dKh + dstep(ks), IDESC_BF16, ks > 0);
#pragma unroll
    for (int ks = 0; ks < 8; ks++)
        mma_ts(tmem + to_s, tmem + TO_QH + ks * 8, dKl + dstep(ks), IDESC_BF16, 1);
#pragma unroll
    for (int ks = 0; ks < 8; ks++)
        mma_ts(tmem + to_s, tmem + TO_QL + ks * 8, dKh + dstep(ks), IDESC_BF16, 1);
    TC_COMMIT(sb + A_MBS + s * 8);
}
#endif

__global__ __launch_bounds__(288, 1) void attn(
        float* __restrict__ out,
        const __grid_constant__ CUtensorMap mKh,
        const __grid_constant__ CUtensorMap mKl,
        const __grid_constant__ CUtensorMap mVt) {
#if HAS_TCGEN05
    char* sm = (char*)smf;
    uint32_t sb = smem_u32(sm);
    int t = threadIdx.x;
    int wid = t >> 5;
    int row = t & 127;
    int half = (t >> 7) & 1;
    int q0 = blockIdx.x * 128;
    int h = blockIdx.y, b = blockIdx.z;
    int bh = b * Hh + h;
    bool is_sw = (t < 256);       // softmax warps 0-7
    bool is_ctl = (t == 256);     // control thread (warp 8 lane 0)

    if (wid == 0) TC_ALLOC(sb + A_PTR, 512);
    if (t == 0) {
        MBAR_INIT(sb + A_MBS + 0, 1);
        MBAR_INIT(sb + A_MBS + 8, 1);
        MBAR_INIT(sb + A_MBO, 1);
        MBAR_INIT(sb + A_KF + 0, 1);
        MBAR_INIT(sb + A_KF + 8, 1);
        FENCE_ASYNC();
    }
    __syncthreads();
    uint32_t tmem;
    asm volatile("ld.shared.b32 %0, [%1];" : "=r"(tmem) : "r"(sb + A_PTR));
    uint32_t tw = tmem + ((uint32_t)(wid & 3) << 21);

    // control: prologue TMAs for tiles 0 and 1
    if (is_ctl) {
        attn_tma6(sb, 0, bh, &mKh, &mKl, &mVt);
        attn_tma6(sb, 1, bh, &mKh, &mKl, &mVt);
    }
    // S-warps: Q into TMEM
    if (is_sw) {
        const uint4* qsrc = (const uint4*)((half == 0 ? g_qh : g_ql) +
                                ((size_t)bh * Ss + q0 + row) * HD);
        uint32_t dstc = (half == 0) ? (tw + TO_QH) : (tw + TO_QL);
        uint32_t rg[32];
#pragma unroll
        for (int hb = 0; hb < 2; hb++) {
#pragma unroll
            for (int j = 0; j < 8; j++) ((uint4*)rg)[j] = qsrc[hb * 8 + j];
            TC_ST_X32(dstc + hb * 32, rg);
        }
        TC_WAIT_ST();
        TC_FENCE_BEFORE();
    }
    __syncthreads();
    // control: S-MMA(0)
    if (is_ctl) {
        TC_FENCE_AFTER();
        attn_smma(tmem, sb, 0);
    }

    float m_ref = -1e30f, l = 0.0f;

    for (int iter = 0; iter < NT; iter++) {
        int su = iter & 1;
        uint32_t to_s = 128 + (uint32_t)su * 128;
        uint32_t stg = sb + su * A_STG;

        // control: issue S(iter+1) early — overlaps softmax(iter)
        if (is_ctl && iter + 1 < NT) attn_smma(tmem, sb, iter + 1);

        float sc[64], pmax = -1e30f;
        if (is_sw) {
            if (iter > 0) MBAR_WAIT(sb + A_MBO, (iter - 1) & 1);  // O stable for rescale
            MBAR_WAIT(sb + A_MBS + su * 8, (iter >> 1) & 1);
            TC_FENCE_AFTER();
            uint32_t* scu = (uint32_t*)sc;
            uint32_t scol = tw + to_s + half * 64;
            TC_LD_X32(scu + 0,  scol + 0);
            TC_LD_X32(scu + 32, scol + 32);
            TC_WAIT_LD();
            pmax = sc[0];
#pragma unroll
            for (int c = 1; c < 64; c++) pmax = fmaxf(pmax, sc[c]);
            ((float*)(sm + A_SMAX))[t] = pmax;
        }
        __syncthreads();   // sync#1: pmax exchange (also orders S-LDTM before P-STTM)
        if (is_sw) {
            float tmax = fmaxf(pmax, ((float*)(sm + A_SMAX))[t ^ 128]);
            bool need = tmax > m_ref + 4.0f;
            float alpha = 1.0f;
            if (need) { alpha = __expf(m_ref - tmax); m_ref = tmax; }
            float psum = 0.0f;
            uint32_t pr[32];
#pragma unroll
            for (int c = 0; c < 32; c++) {
                float p0 = __expf(sc[2 * c] - m_ref);
                float p1 = __expf(sc[2 * c + 1] - m_ref);
                psum += p0 + p1;
                pr[c] = h2_as_u32(__float22half2_rn(make_float2(p0, p1)));
            }
            ((float*)(sm + A_SSUM))[t] = psum;
            TC_ST_X32(tw + to_s + half * 32, pr);   // P aliases S cols 0-63
            if (iter > 0 && __any_sync(0xffffffffu, need)) {
#pragma unroll
                for (int cb = 0; cb < 2; cb++) {
                    uint32_t og[32];
                    TC_LD_X32(og, tw + TO_O + half * 64 + cb * 32);
                    TC_WAIT_LD();
                    float* of = (float*)og;
#pragma unroll
                    for (int j = 0; j < 32; j++) of[j] *= alpha;
                    TC_ST_X32(tw + TO_O + half * 64 + cb * 32, og);
                }
            }
            TC_WAIT_ST();
            TC_FENCE_BEFORE();
            l = l * alpha + psum;   // other half added after sync
        }
        __syncthreads();   // sync#2: P ready for PV
        if (is_sw) l += ((float*)(sm + A_SSUM))[t ^ 128];
        if (is_ctl) {
            TC_FENCE_AFTER();
            uint64_t dV = MK_DESC(stg + AS_V);
#pragma unroll
            for (int ks = 0; ks < 8; ks++)
                mma_ts(tmem + TO_O, tmem + to_s + ks * 8, dV + dstep(ks), IDESC_FP16,
                       (iter > 0) || (ks > 0));
            TC_COMMIT(sb + A_MBO);
            if (iter + 2 < NT) {
                MBAR_WAIT(sb + A_MBO, iter & 1);  // PV(iter) done -> stage su reusable
                attn_tma6(sb, iter + 2, bh, &mKh, &mKl, &mVt);
            }
        }
    }

    MBAR_WAIT(sb + A_MBO, (NT - 1) & 1);
    TC_FENCE_AFTER();
    if (is_sw) {
        float inv = 1.0f / l;
        float* dst = out + ((size_t)b * Ss + q0 + row) * DM + h * HD + half * 64;
#pragma unroll
        for (int cb = 0; cb < 2; cb++) {
            uint32_t og[32];
            TC_LD_X32(og, tw + TO_O + half * 64 + cb * 32);
            TC_WAIT_LD();
            float* of = (float*)og;
#pragma unroll
            for (int j = 0; j < 32; j += 4) {
                float4 o = make_float4(of[j] * inv, of[j + 1] * inv,
                                       of[j + 2] * inv, of[j + 3] * inv);
                *(float4*)(dst + cb * 32 + j) = o;
            }
        }
    }
    __syncthreads();
    if (wid == 0) TC_DEALLOC(tmem, 512);
#endif
}

// ---- Host ----
typedef CUresult (*PFN_encodeTiled)(CUtensorMap*, CUtensorMapDataType, cuuint32_t,
                                    void*, const cuuint64_t*, const cuuint64_t*,
                                    const cuuint32_t*, const cuuint32_t*,
                                    CUtensorMapInterleave, CUtensorMapSwizzle,
                                    CUtensorMapL2promotion, CUtensorMapFloatOOBfill);
static PFN_encodeTiled get_encoder() {
    static PFN_encodeTiled fn = nullptr;
    if (!fn) {
        cudaDriverEntryPointQueryResult qr;
        cudaGetDriverEntryPointByVersion("cuTensorMapEncodeTiled", (void**)&fn,
                                         12000, cudaEnableDefault, &qr);
    }
    return fn;
}
static void enc(CUtensorMap* m, void* base, int nd, uint64_t d0, uint64_t d1, uint64_t d2,
                uint32_t b0, uint32_t b1, CUtensorMapDataType dt) {
    cuuint64_t dims[3] = {d0, d1, d2};
    cuuint64_t strides[2] = {d0 * 2, d0 * d1 * 2};
    cuuint32_t box[3] = {b0, b1, 1};
    cuuint32_t es[3] = {1, 1, 1};
    get_encoder()(m, dt, nd, base, dims, strides, box, es,
                  CU_TENSOR_MAP_INTERLEAVE_NONE, CU_TENSOR_MAP_SWIZZLE_128B,
                  CU_TENSOR_MAP_L2_PROMOTION_L2_128B, CU_TENSOR_MAP_FLOAT_OOB_FILL_NONE);
}

extern "C" void kernel_launch(void* const* d_in, const int* in_sizes, int n_in,
                              void* d_out, int out_size) {
    const float* hs  = (const float*)d_in[0];
    const float* w   = (const float*)d_in[1];
    const float* bqv = (const float*)d_in[2];
    const float* wqn = (const float*)d_in[3];
    const float* wkn = (const float*)d_in[4];
    const float* cs  = (const float*)d_in[5];
    const float* sn  = (const float*)d_in[6];
    const int*   tsl = (const int*)d_in[7];
    float* out = (float*)d_out;

    __nv_bfloat16 *ah, *al, *wh, *wl, *kh, *kl;
    __half *vt;
    cudaGetSymbolAddress((void**)&ah, g_Ah);
    cudaGetSymbolAddress((void**)&al, g_Al);
    cudaGetSymbolAddress((void**)&wh, g_Wh);
    cudaGetSymbolAddress((void**)&wl, g_Wl);
    cudaGetSymbolAddress((void**)&kh, g_kh);
    cudaGetSymbolAddress((void**)&kl, g_kl);
    cudaGetSymbolAddress((void**)&vt, g_vt);

    CUtensorMap mAh, mAl, mWh, mWl, mKh, mKl, mVt;
    enc(&mAh, ah, 2, KD, MR, 1, 64, 128, CU_TENSOR_MAP_DATA_TYPE_BFLOAT16);
    enc(&mAl, al, 2, KD, MR, 1, 64, 128, CU_TENSOR_MAP_DATA_TYPE_BFLOAT16);
    enc(&mWh, wh, 2, KD, N3, 1, 64, 128, CU_TENSOR_MAP_DATA_TYPE_BFLOAT16);
    enc(&mWl, wl, 2, KD, N3, 1, 64, 128, CU_TENSOR_MAP_DATA_TYPE_BFLOAT16);
    enc(&mKh, kh, 3, HD, Ss, Bb * Hh, 64, 128, CU_TENSOR_MAP_DATA_TYPE_BFLOAT16);
    enc(&mKl, kl, 3, HD, Ss, Bb * Hh, 64, 128, CU_TENSOR_MAP_DATA_TYPE_BFLOAT16);
    enc(&mVt, vt, 3, Ss, HD, Bb * Hh, 64, 128, CU_TENSOR_MAP_DATA_TYPE_FLOAT16);

    int na4 = MR * KD / 4;
    int nw4 = N3 * KD / 4;
    int ntot = na4 + nw4;
    cvt_split2<<<(ntot + 255) / 256, 256>>>(hs, w, ah, al, wh, wl, na4, ntot);

    cudaFuncSetAttribute(qkv_gemm_tc, cudaFuncAttributeMaxDynamicSharedMemorySize, GEMM_SMEM);
    qkv_gemm_tc<<<dim3(MR / 128, N3 / 512), 256, GEMM_SMEM>>>(bqv, wqn, wkn, cs, sn, tsl,
                                                              mAh, mAl, mWh, mWl);

    v_transpose<<<dim3(Ss / 128, Bb * Hh), 256>>>();

    cudaFuncSetAttribute(attn, cudaFuncAttributeMaxDynamicSharedMemorySize, ATT_SMEM);
    attn<<<dim3(Ss / 128, Hh, Bb), 288, ATT_SMEM>>>(out, mKh, mKl, mVt);
}

// round 15
// speedup vs baseline: 1.1198x; 1.1198x over previous
#include <cuda_runtime.h>
#include <cuda.h>
#include <cuda_bf16.h>
#include <cuda_fp16.h>
#include <cstdint>

#if defined(__CUDA_ARCH_FEAT_SM103_ALL) || defined(__CUDA_ARCH_FEAT_SM100_ALL) || \
    (defined(__CUDA_ARCH_SPECIFIC__) && (__CUDA_ARCH_SPECIFIC__ >= 1000))
#define HAS_TCGEN05 1
#else
#define HAS_TCGEN05 0
#endif

#define Bb 2
#define Ss 2304
#define Hh 24
#define HD 128
#define DM 3072
#define N3 9216
#define KD 3072
#define MR (Bb*Ss)

__device__ alignas(128) __nv_bfloat16 g_Ah[(size_t)MR * KD];
__device__ alignas(128) __nv_bfloat16 g_Al[(size_t)MR * KD];
__device__ alignas(128) __nv_bfloat16 g_Wh[(size_t)N3 * KD];
__device__ alignas(128) __nv_bfloat16 g_Wl[(size_t)N3 * KD];
#define NBH ((size_t)Bb * Hh * Ss * HD)
__device__ alignas(128) __nv_bfloat16 g_qh[NBH];
__device__ alignas(128) __nv_bfloat16 g_ql[NBH];
__device__ alignas(128) __nv_bfloat16 g_kh[NBH];
__device__ alignas(128) __nv_bfloat16 g_kl[NBH];
__device__ alignas(128) __half g_vh[NBH];
__device__ alignas(128) __half g_vt[NBH];

__device__ __forceinline__ uint32_t smem_u32(const void* p) {
    uint32_t a;
    asm("{ .reg .u64 t; cvta.to.shared.u64 t, %1; cvt.u32.u64 %0, t; }" : "=r"(a) : "l"(p));
    return a;
}
__device__ __forceinline__ uint32_t h2_as_u32(__half2 h) {
    uint32_t u;
    asm("mov.b32 %0, %1;" : "=r"(u) : "r"(*(uint32_t*)&h));
    return u;
}
#define MK_DESC(addr) ((uint64_t(2) << 61) | (uint64_t(1) << 46) | (uint64_t(64) << 32) | \
                       (uint64_t(1) << 16) | ((uint64_t)((addr) >> 4) & 0x3FFF))
#define MBAR_INIT(m, c) asm volatile("mbarrier.init.shared.b64 [%0], %1;" :: "r"(m), "r"(c) : "memory")
#define MBAR_WAIT(m, p) asm volatile( \
    "{\n\t.reg .pred P1;\n\t" \
    "WL%=:\n\tmbarrier.try_wait.parity.acquire.cta.shared::cta.b64 P1, [%0], %1, 0x989680;\n\t" \
    "@P1 bra.uni WD%=;\n\tbra.uni WL%=;\n\tWD%=:\n\t}" \
    :: "r"(m), "r"(p) : "memory")
#define MBAR_EXPECT_TX(m, n) asm volatile( \
    "mbarrier.arrive.expect_tx.shared.b64 _, [%0], %1;" :: "r"(m), "r"(n) : "memory")
#define TMA_3D(dst, map, x, y, z, mb) asm volatile( \
    "cp.async.bulk.tensor.3d.shared::cta.global.tile.mbarrier::complete_tx::bytes " \
    "[%0], [%1, {%2, %3, %4}], [%5];" \
    :: "r"(dst), "l"(map), "r"(x), "r"(y), "r"(z), "r"(mb) : "memory")
#define TMA_2D_CG2(dst, map, x, y, mb) asm volatile( \
    "{\n\t.reg .b32 lb;\n\tand.b32 lb, %4, 0xFEFFFFFF;\n\t" \
    "cp.async.bulk.tensor.2d.cta_group::2.shared::cluster.global.tile." \
    "mbarrier::complete_tx::bytes [%0], [%1, {%2, %3}], [lb];\n\t}" \
    :: "r"(dst), "l"(map), "r"(x), "r"(y), "r"(mb) : "memory")
#define CLUSTER_SYNC() do { \
    asm volatile("barrier.cluster.arrive.aligned;" ::: "memory"); \
    asm volatile("barrier.cluster.wait.aligned;" ::: "memory"); } while (0)

#if HAS_TCGEN05
__device__ __forceinline__ void mma_ss_cg2(uint32_t d, uint64_t a, uint64_t b,
                                           uint32_t idesc, uint32_t en) {
    asm volatile(
        "{\n\t.reg .pred p;\n\tsetp.ne.u32 p, %4, 0;\n\t"
        "tcgen05.mma.cta_group::2.kind::f16 [%0], %1, %2, %3, "
        "{%5, %5, %5, %5, %5, %5, %5, %5}, p;\n\t}"
        :: "r"(d), "l"(a), "l"(b), "r"(idesc), "r"(en), "r"(0u) : "memory");
}
__device__ __forceinline__ void mma_ts(uint32_t d, uint32_t a, uint64_t b,
                                       uint32_t idesc, uint32_t en) {
    asm volatile(
        "{\n\t.reg .pred p;\n\tsetp.ne.u32 p, %4, 0;\n\t"
        "tcgen05.mma.cta_group::1.kind::f16 [%0], [%1], %2, %3, {%5, %5, %5, %5}, p;\n\t}"
        :: "r"(d), "r"(a), "l"(b), "r"(idesc), "r"(en), "r"(0u) : "memory");
}
#define TC_COMMIT(m) asm volatile( \
    "tcgen05.commit.cta_group::1.mbarrier::arrive::one.shared::cluster.b64 [%0];" :: "r"(m) : "memory")
#define TC_COMMIT_MC2(m) asm volatile( \
    "tcgen05.commit.cta_group::2.mbarrier::arrive::one.shared::cluster.multicast::cluster.b64 [%0], %1;" \
    :: "r"(m), "h"((uint16_t)0x3) : "memory")
#define TC_ALLOC(sm, n)  asm volatile("tcgen05.alloc.cta_group::1.sync.aligned.shared::cta.b32 [%0], %1;" :: "r"(sm), "r"(n) : "memory")
#define TC_DEALLOC(t, n) asm volatile("tcgen05.dealloc.cta_group::1.sync.aligned.b32 %0, %1;" :: "r"(t), "r"(n))
#define TC_ALLOC_CG2(sm, n)  asm volatile("tcgen05.alloc.cta_group::2.sync.aligned.shared::cta.b32 [%0], %1;" :: "r"(sm), "r"(n) : "memory")
#define TC_DEALLOC_CG2(t, n) asm volatile("tcgen05.dealloc.cta_group::2.sync.aligned.b32 %0, %1;" :: "r"(t), "r"(n))
#define TC_RELINQ_CG2() asm volatile("tcgen05.relinquish_alloc_permit.cta_group::2.sync.aligned;")
#define TC_FENCE_AFTER() asm volatile("tcgen05.fence::after_thread_sync;" ::: "memory")
#define TC_FENCE_BEFORE() asm volatile("tcgen05.fence::before_thread_sync;" ::: "memory")
#define TC_WAIT_LD()     asm volatile("tcgen05.wait::ld.sync.aligned;" ::: "memory")
#define TC_WAIT_ST()     asm volatile("tcgen05.wait::st.sync.aligned;" ::: "memory")
#define FENCE_ASYNC()    asm volatile("fence.proxy.async.shared::cta;" ::: "memory")

#define TC_LD_X32(r, a) asm volatile( \
    "tcgen05.ld.sync.aligned.32x32b.x32.b32 " \
    "{%0, %1, %2, %3, %4, %5, %6, %7, %8, %9, %10, %11, %12, %13, %14, %15, " \
    "%16, %17, %18, %19, %20, %21, %22, %23, %24, %25, %26, %27, %28, %29, %30, %31}, [%32];" \
    : "=r"((r)[0]), "=r"((r)[1]), "=r"((r)[2]), "=r"((r)[3]), "=r"((r)[4]), "=r"((r)[5]), \
      "=r"((r)[6]), "=r"((r)[7]), "=r"((r)[8]), "=r"((r)[9]), "=r"((r)[10]), "=r"((r)[11]), \
      "=r"((r)[12]), "=r"((r)[13]), "=r"((r)[14]), "=r"((r)[15]), "=r"((r)[16]), "=r"((r)[17]), \
      "=r"((r)[18]), "=r"((r)[19]), "=r"((r)[20]), "=r"((r)[21]), "=r"((r)[22]), "=r"((r)[23]), \
      "=r"((r)[24]), "=r"((r)[25]), "=r"((r)[26]), "=r"((r)[27]), "=r"((r)[28]), "=r"((r)[29]), \
      "=r"((r)[30]), "=r"((r)[31]) : "r"(a))

#define TC_ST_X32(a, r) asm volatile( \
    "tcgen05.st.sync.aligned.32x32b.x32.b32 [%0], " \
    "{%1, %2, %3, %4, %5, %6, %7, %8, %9, %10, %11, %12, %13, %14, %15, %16, " \
    "%17, %18, %19, %20, %21, %22, %23, %24, %25, %26, %27, %28, %29, %30, %31, %32};" \
    :: "r"(a), \
       "r"((r)[0]), "r"((r)[1]), "r"((r)[2]), "r"((r)[3]), "r"((r)[4]), "r"((r)[5]), \
       "r"((r)[6]), "r"((r)[7]), "r"((r)[8]), "r"((r)[9]), "r"((r)[10]), "r"((r)[11]), \
       "r"((r)[12]), "r"((r)[13]), "r"((r)[14]), "r"((r)[15]), "r"((r)[16]), "r"((r)[17]), \
       "r"((r)[18]), "r"((r)[19]), "r"((r)[20]), "r"((r)[21]), "r"((r)[22]), "r"((r)[23]), \
       "r"((r)[24]), "r"((r)[25]), "r"((r)[26]), "r"((r)[27]), "r"((r)[28]), "r"((r)[29]), \
       "r"((r)[30]), "r"((r)[31]) : "memory")
#endif

// ---- Kernel 0: fused fp32 -> (hi,lo) bf16 ----
__global__ __launch_bounds__(256) void cvt_split2(const float* __restrict__ a,
                                                  const float* __restrict__ w,
                                                  __nv_bfloat16* __restrict__ ah,
                                                  __nv_bfloat16* __restrict__ al,
                                                  __nv_bfloat16* __restrict__ wh,
                                                  __nv_bfloat16* __restrict__ wl,
                                                  int na4, int ntot) {
    int i = blockIdx.x * 256 + threadIdx.x;
    if (i >= ntot) return;
    const float* x; __nv_bfloat16 *hi, *lo; int j;
    if (i < na4) { x = a; hi = ah; lo = al; j = i; }
    else         { x = w; hi = wh; lo = wl; j = i - na4; }
    float4 v = ((const float4*)x)[j];
    __nv_bfloat16 h0 = __float2bfloat16(v.x), h1 = __float2bfloat16(v.y);
    __nv_bfloat16 h2 = __float2bfloat16(v.z), h3 = __float2bfloat16(v.w);
    __nv_bfloat16 l0 = __float2bfloat16(v.x - __bfloat162float(h0));
    __nv_bfloat16 l1 = __float2bfloat16(v.y - __bfloat162float(h1));
    __nv_bfloat16 l2 = __float2bfloat16(v.z - __bfloat162float(h2));
    __nv_bfloat16 l3 = __float2bfloat16(v.w - __bfloat162float(h3));
    ((__nv_bfloat162*)hi)[2 * j] = __nv_bfloat162(h0, h1);
    ((__nv_bfloat162*)hi)[2 * j + 1] = __nv_bfloat162(h2, h3);
    ((__nv_bfloat162*)lo)[2 * j] = __nv_bfloat162(l0, l1);
    ((__nv_bfloat162*)lo)[2 * j + 1] = __nv_bfloat162(l2, l3);
}

// ---- Kernel 1: cg2 GEMM, 256x512 pair tile, fused epilogue (R13; log2e folded into qscale) ----
#define GS_AH 0
#define GS_AL 16384
#define GS_W0H 32768
#define GS_W0L 49152
#define GS_W1H 65536
#define GS_W1L 81920
#define G_STG 98304
#define SM_BIAS  196608
#define SM_TMEMP 198656
#define SM_MB    198664
#define SM_KF    198680
#define GEMM_SMEM 198784
#define IDESC_CG2N256 0x10400490u
#define IDESC_BF16 0x8200490u
#define IDESC_FP16 0x8200010u
#define NCH 48

extern __shared__ float smf[];

__global__ __launch_bounds__(256) __cluster_dims__(2, 1, 1)
void qkv_gemm_tc(const float* __restrict__ bias,
                 const float* __restrict__ wq, const float* __restrict__ wk,
                 const float* __restrict__ cs, const float* __restrict__ sn,
                 const int* __restrict__ tsl,
                 const __grid_constant__ CUtensorMap mAh,
                 const __grid_constant__ CUtensorMap mAl,
                 const __grid_constant__ CUtensorMap mWh,
                 const __grid_constant__ CUtensorMap mWl) {
#if HAS_TCGEN05
    char* sm = (char*)smf;
    uint32_t sb = smem_u32(sm);
    int t = threadIdx.x;
    int wid = t >> 5;
    int rank = blockIdx.x & 1;
    int m0 = (blockIdx.x >> 1) * 256 + rank * 128;
    int n0 = blockIdx.y * 512;

    if (wid == 0) TC_ALLOC_CG2(sb + SM_TMEMP, 512);
    if (t == 0) {
        MBAR_INIT(sb + SM_MB + 0, 1);
        MBAR_INIT(sb + SM_MB + 8, 1);
        MBAR_INIT(sb + SM_KF + 0, 1);
        MBAR_INIT(sb + SM_KF + 8, 1);
        FENCE_ASYNC();
        if (rank == 0) {
            MBAR_EXPECT_TX(sb + SM_KF + 0, 196608u);
            MBAR_EXPECT_TX(sb + SM_KF + 8, 196608u);
        }
    }
    ((float*)(sm + SM_BIAS))[t] = bias[n0 + t];
    ((float*)(sm + SM_BIAS))[t + 256] = bias[n0 + t + 256];
    __syncthreads();
    CLUSTER_SYNC();
    uint32_t tmem;
    asm volatile("ld.shared.b32 %0, [%1];" : "=r"(tmem) : "r"(sb + SM_TMEMP));

    if (t == 0) {
#pragma unroll
        for (int c = 0; c < 2; c++) {
            uint32_t stg = sb + c * G_STG, kfb = sb + SM_KF + c * 8;
            int k0 = c * 64;
            TMA_2D_CG2(stg + GS_AH,  &mAh, k0, m0, kfb);
            TMA_2D_CG2(stg + GS_AL,  &mAl, k0, m0, kfb);
            TMA_2D_CG2(stg + GS_W0H, &mWh, k0, n0 + rank * 128, kfb);
            TMA_2D_CG2(stg + GS_W0L, &mWl, k0, n0 + rank * 128, kfb);
            TMA_2D_CG2(stg + GS_W1H, &mWh, k0, n0 + 256 + rank * 128, kfb);
            TMA_2D_CG2(stg + GS_W1L, &mWl, k0, n0 + 256 + rank * 128, kfb);
        }
        const int ca[3] = {0, 0, 1}, cw[3] = {0, 1, 0};
        for (int i = 0; i < NCH; i++) {
            int s = i & 1;
            if (rank == 0) {
                MBAR_WAIT(sb + SM_KF + s * 8, (i >> 1) & 1);
                if (i + 2 < NCH) MBAR_EXPECT_TX(sb + SM_KF + s * 8, 196608u);
                uint32_t stg = sb + s * G_STG;
                uint64_t dA[2]  = {MK_DESC(stg + GS_AH), MK_DESC(stg + GS_AL)};
                uint64_t dW0[2] = {MK_DESC(stg + GS_W0H), MK_DESC(stg + GS_W0L)};
                uint64_t dW1[2] = {MK_DESC(stg + GS_W1H), MK_DESC(stg + GS_W1L)};
#pragma unroll
                for (int c3 = 0; c3 < 3; c3++) {
                    uint64_t b0 = cw[c3] ? dW0[1] : dW0[0];
                    uint64_t b1 = cw[c3] ? dW1[1] : dW1[0];
                    uint64_t aa = dA[ca[c3]];
#pragma unroll
                    for (int ks = 0; ks < 4; ks++) {
                        uint32_t en = (i | c3 | ks) ? 1u : 0u;
                        mma_ss_cg2(tmem,       aa + ks * 2, b0 + ks * 2, IDESC_CG2N256, en);
                        mma_ss_cg2(tmem + 256, aa + ks * 2, b1 + ks * 2, IDESC_CG2N256, en);
                    }
                }
                TC_COMMIT_MC2(sb + SM_MB + s * 8);
            }
            if (i >= 1 && i + 1 < NCH) {
                int s2 = (i + 1) & 1;
                MBAR_WAIT(sb + SM_MB + s2 * 8, ((i - 1) >> 1) & 1);
                uint32_t stg = sb + s2 * G_STG, kfb = sb + SM_KF + s2 * 8;
                int k0 = (i + 1) * 64;
                TMA_2D_CG2(stg + GS_AH,  &mAh, k0, m0, kfb);
                TMA_2D_CG2(stg + GS_AL,  &mAl, k0, m0, kfb);
                TMA_2D_CG2(stg + GS_W0H, &mWh, k0, n0 + rank * 128, kfb);
                TMA_2D_CG2(stg + GS_W0L, &mWl, k0, n0 + rank * 128, kfb);
                TMA_2D_CG2(stg + GS_W1H, &mWh, k0, n0 + 256 + rank * 128, kfb);
                TMA_2D_CG2(stg + GS_W1L, &mWl, k0, n0 + 256 + rank * 128, kfb);
            }
        }
        MBAR_WAIT(sb + SM_MB + 0, 1);
        MBAR_WAIT(sb + SM_MB + 8, 1);
    }
    __syncthreads();
    TC_FENCE_AFTER();

    {
        int r = t & 127;
        int m = m0 + r;
        int b = m / Ss, s2 = m % Ss;
        int sec = n0 / DM;
        int h0 = (n0 % DM) / HD;
        uint32_t tw = tmem + ((uint32_t)(wid & 3) << 21);
        int T = tsl[0];
        bool rope = (s2 >= T);
        int p = s2 - T;
#pragma unroll
        for (int hc2 = 0; hc2 < 2; hc2++) {
            int hc = (t >> 7) + hc2 * 2;
            uint32_t cbase = tw + hc * 128;
            const float* bs = (const float*)(sm + SM_BIAS) + hc * 128;
            size_t obase = ((size_t)(b * Hh + h0 + hc) * Ss + s2) * (size_t)HD;

            if (sec == 2) {
                __half* dv = g_vh + obase;
#pragma unroll
                for (int cb = 0; cb < 4; cb++) {
                    uint32_t rg[32];
                    TC_LD_X32(rg, cbase + cb * 32);
                    TC_WAIT_LD();
                    __half hb[32];
#pragma unroll
                    for (int j = 0; j < 32; j += 2) {
                        float a0 = __uint_as_float(rg[j]) + bs[cb * 32 + j];
                        float a1 = __uint_as_float(rg[j + 1]) + bs[cb * 32 + j + 1];
                        *(__half2*)(hb + j) = __float22half2_rn(make_float2(a0, a1));
                    }
#pragma unroll
                    for (int q4 = 0; q4 < 4; q4++)
                        *(uint4*)(dv + cb * 32 + q4 * 8) = *(uint4*)(hb + q4 * 8);
                }
            } else {
                const float* wn = (sec == 0) ? wq : wk;
                float ssq = 0.0f;
#pragma unroll
                for (int cb = 0; cb < 4; cb++) {
                    uint32_t rg[32];
                    TC_LD_X32(rg, cbase + cb * 32);
                    TC_WAIT_LD();
#pragma unroll
                    for (int j = 0; j < 32; j++) {
                        float a = __uint_as_float(rg[j]) + bs[cb * 32 + j];
                        ssq += a * a;
                    }
                }
                float rms = rsqrtf(ssq * (1.0f / 128.0f) + 1e-6f);
                // qscale = (1/sqrt(128)) * log2(e): attention uses exp2
                float qscale = (sec == 0) ? 0.12752050778924437f : 1.0f;
                __nv_bfloat16* dh = ((sec == 0) ? g_qh : g_kh) + obase;
                __nv_bfloat16* dl = ((sec == 0) ? g_ql : g_kl) + obase;
#pragma unroll
                for (int cb = 0; cb < 4; cb++) {
                    uint32_t rg[32];
                    TC_LD_X32(rg, cbase + cb * 32);
                    TC_WAIT_LD();
                    float y[32];
#pragma unroll
                    for (int j = 0; j < 32; j++)
                        y[j] = (__uint_as_float(rg[j]) + bs[cb * 32 + j]) * rms * wn[cb * 32 + j];
                    if (rope) {
#pragma unroll
                        for (int jj = 0; jj < 16; jj++) {
                            float c = cs[p * 64 + cb * 16 + jj], sv = sn[p * 64 + cb * 16 + jj];
                            float x1 = y[2 * jj], x2 = y[2 * jj + 1];
                            y[2 * jj] = x1 * c - x2 * sv;
                            y[2 * jj + 1] = x2 * c + x1 * sv;
                        }
                    }
                    __nv_bfloat16 hb[32], lb[32];
#pragma unroll
                    for (int j = 0; j < 32; j++) {
                        float v = y[j] * qscale;
                        __nv_bfloat16 hv = __float2bfloat16(v);
                        hb[j] = hv;
                        lb[j] = __float2bfloat16(v - __bfloat162float(hv));
                    }
#pragma unroll
                    for (int q4 = 0; q4 < 4; q4++) {
                        *(uint4*)(dh + cb * 32 + q4 * 8) = *(uint4*)(hb + q4 * 8);
                        *(uint4*)(dl + cb * 32 + q4 * 8) = *(uint4*)(lb + q4 * 8);
                    }
                }
            }
        }
    }
    __syncthreads();
    if (wid == 0) { TC_RELINQ_CG2(); TC_DEALLOC_CG2(tmem, 512); }
    CLUSTER_SYNC();
#endif
}

// ---- Kernel 2b: V transpose ----
__global__ __launch_bounds__(256) void v_transpose() {
    __shared__ __half ts[128 * 129];
    int t = threadIdx.x;
    int s0 = blockIdx.x * 128;
    int bh = blockIdx.y;
    const __half* src = g_vh + ((size_t)bh * Ss + s0) * HD;
#pragma unroll
    for (int i = 0; i < 8; i++) {
        int idx = t + i * 256;
        int s = idx >> 4, c8 = idx & 15;
        uint4 v = *(const uint4*)(src + s * HD + c8 * 8);
        __half tmp[8];
        *(uint4*)tmp = v;
#pragma unroll
        for (int j = 0; j < 8; j++) ts[s * 129 + c8 * 8 + j] = tmp[j];
    }
    __syncthreads();
    __half* dst = g_vt + (size_t)bh * HD * Ss;
#pragma unroll
    for (int i = 0; i < 8; i++) {
        int idx = t + i * 256;
        int d = idx >> 4, s8 = idx & 15;
        __half o[8];
#pragma unroll
        for (int j = 0; j < 8; j++) o[j] = ts[(s8 * 8 + j) * 129 + d];
        *(uint4*)(dst + (size_t)d * Ss + s0 + s8 * 8) = *(uint4*)o;
    }
}

// ---- Kernel 3: attention — R13 structure, exp2-domain softmax ----
#define A_STG 98304
#define AS_KH 0
#define AS_KL 32768
#define AS_V  65536
#define A_SMAX 196608
#define A_SSUM 197632
#define A_PTR  198656
#define A_MBS  198664
#define A_MBO  198672
#define A_KF   198680
#define ATT_SMEM 198784
#define NT 18
#define TO_O  0
#define TO_S  128
#define TO_P  256
#define TO_QH 320
#define TO_QL 384

__device__ __forceinline__ uint32_t dstep(int ks) {
    return (uint32_t)((ks >> 2) * 1024 + (ks & 3) * 2);
}

__global__ __launch_bounds__(256, 1) void attn(
        float* __restrict__ out,
        const __grid_constant__ CUtensorMap mKh,
        const __grid_constant__ CUtensorMap mKl,
        const __grid_constant__ CUtensorMap mVt) {
#if HAS_TCGEN05
    char* sm = (char*)smf;
    uint32_t sb = smem_u32(sm);
    int t = threadIdx.x;
    int wid = t >> 5;
    int row = t & 127;
    int half = t >> 7;
    int q0 = blockIdx.x * 128;
    int h = blockIdx.y, b = blockIdx.z;
    int bh = b * Hh + h;

    if (wid == 0) TC_ALLOC(sb + A_PTR, 512);
    if (t == 0) {
        MBAR_INIT(sb + A_MBS, 1);
        MBAR_INIT(sb + A_MBO, 1);
        MBAR_INIT(sb + A_KF + 0, 1);
        MBAR_INIT(sb + A_KF + 8, 1);
        FENCE_ASYNC();
        MBAR_EXPECT_TX(sb + A_KF, 98304u);
        TMA_3D(sb + AS_KH,         &mKh, 0,  0, bh, sb + A_KF);
        TMA_3D(sb + AS_KH + 16384, &mKh, 64, 0, bh, sb + A_KF);
        TMA_3D(sb + AS_KL,         &mKl, 0,  0, bh, sb + A_KF);
        TMA_3D(sb + AS_KL + 16384, &mKl, 64, 0, bh, sb + A_KF);
        TMA_3D(sb + AS_V,          &mVt, 0,  0, bh, sb + A_KF);
        TMA_3D(sb + AS_V + 16384,  &mVt, 64, 0, bh, sb + A_KF);
    }
    __syncthreads();
    uint32_t tmem;
    asm volatile("ld.shared.b32 %0, [%1];" : "=r"(tmem) : "r"(sb + A_PTR));
    uint32_t tw = tmem + ((uint32_t)(wid & 3) << 21);

    {
        const uint4* qsrc = (const uint4*)((half == 0 ? g_qh : g_ql) +
                                ((size_t)bh * Ss + q0 + row) * HD);
        uint32_t dstc = (half == 0) ? (tw + TO_QH) : (tw + TO_QL);
        uint32_t rg[32];
#pragma unroll
        for (int hb = 0; hb < 2; hb++) {
#pragma unroll
            for (int j = 0; j < 8; j++) ((uint4*)rg)[j] = qsrc[hb * 8 + j];
            TC_ST_X32(dstc + hb * 32, rg);
        }
        TC_WAIT_ST();
    }
    TC_FENCE_BEFORE();
    __syncthreads();

    float m_ref = -1e30f, l = 0.0f;

    for (int iter = 0; iter < NT; iter++) {
        int s = iter & 1;
        uint32_t stg = sb + s * A_STG;

        if (t == 0) {
            TC_FENCE_AFTER();
            MBAR_WAIT(sb + A_KF + s * 8, (iter >> 1) & 1);
            uint64_t dKh = MK_DESC(stg + AS_KH);
            uint64_t dKl = MK_DESC(stg + AS_KL);
#pragma unroll
            for (int ks = 0; ks < 8; ks++)
                mma_ts(tmem + TO_S, tmem + TO_QH + ks * 8, dKh + dstep(ks), IDESC_BF16, ks > 0);
#pragma unroll
            for (int ks = 0; ks < 8; ks++)
                mma_ts(tmem + TO_S, tmem + TO_QH + ks * 8, dKl + dstep(ks), IDESC_BF16, 1);
#pragma unroll
            for (int ks = 0; ks < 8; ks++)
                mma_ts(tmem + TO_S, tmem + TO_QL + ks * 8, dKh + dstep(ks), IDESC_BF16, 1);
            TC_COMMIT(sb + A_MBS);
        }

        if (iter > 0) MBAR_WAIT(sb + A_MBO, (iter - 1) & 1);

        if (t == 0 && iter + 1 < NT) {
            int s2 = (iter + 1) & 1;
            uint32_t st2 = sb + s2 * A_STG;
            int kt = (iter + 1) * 128;
            MBAR_EXPECT_TX(sb + A_KF + s2 * 8, 98304u);
            TMA_3D(st2 + AS_KH,         &mKh, 0,  kt, bh, sb + A_KF + s2 * 8);
            TMA_3D(st2 + AS_KH + 16384, &mKh, 64, kt, bh, sb + A_KF + s2 * 8);
            TMA_3D(st2 + AS_KL,         &mKl, 0,  kt, bh, sb + A_KF + s2 * 8);
            TMA_3D(st2 + AS_KL + 16384, &mKl, 64, kt, bh, sb + A_KF + s2 * 8);
            TMA_3D(st2 + AS_V,          &mVt, kt,      0, bh, sb + A_KF + s2 * 8);
            TMA_3D(st2 + AS_V + 16384,  &mVt, kt + 64, 0, bh, sb + A_KF + s2 * 8);
        }

        // softmax in exp2 domain (log2(e) folded into Q scale upstream)
        {
            MBAR_WAIT(sb + A_MBS, iter & 1);
            TC_FENCE_AFTER();
            float sc[64];
            uint32_t* scu = (uint32_t*)sc;
            uint32_t scol = tw + TO_S + half * 64;
            TC_LD_X32(scu + 0,  scol + 0);
            TC_LD_X32(scu + 32, scol + 32);
            TC_WAIT_LD();
            float pmax = sc[0];
#pragma unroll
            for (int c = 1; c < 64; c++) pmax = fmaxf(pmax, sc[c]);
            ((float*)(sm + A_SMAX))[t] = pmax;
            __syncthreads();
            float tmax = fmaxf(pmax, ((float*)(sm + A_SMAX))[t ^ 128]);
            bool need = tmax > m_ref + 6.0f;   // log2 units; fp16 P safe to 2^16
            float alpha = 1.0f;
            if (need) { alpha = exp2f(m_ref - tmax); m_ref = tmax; }
            float psum = 0.0f;
            uint32_t pr[32];
#pragma unroll
            for (int c = 0; c < 32; c++) {
                float p0 = exp2f(sc[2 * c] - m_ref);
                float p1 = exp2f(sc[2 * c + 1] - m_ref);
                psum += p0 + p1;
                pr[c] = h2_as_u32(__float22half2_rn(make_float2(p0, p1)));
            }
            ((float*)(sm + A_SSUM))[t] = psum;
            TC_ST_X32(tw + TO_P + half * 32, pr);
            if (iter > 0 && __any_sync(0xffffffffu, need)) {
#pragma unroll
                for (int cb = 0; cb < 2; cb++) {
                    uint32_t og[32];
                    TC_LD_X32(og, tw + TO_O + half * 64 + cb * 32);
                    TC_WAIT_LD();
                    float* of = (float*)og;
#pragma unroll
                    for (int j = 0; j < 32; j++) of[j] *= alpha;
                    TC_ST_X32(tw + TO_O + half * 64 + cb * 32, og);
                }
            }
            TC_WAIT_ST();
            TC_FENCE_BEFORE();
            __syncthreads();
            l = l * alpha + psum + ((float*)(sm + A_SSUM))[t ^ 128];
        }

        if (t == 0) {
            TC_FENCE_AFTER();
            uint64_t dV = MK_DESC(stg + AS_V);
#pragma unroll
            for (int ks = 0; ks < 8; ks++)
                mma_ts(tmem + TO_O, tmem + TO_P + ks * 8, dV + dstep(ks), IDESC_FP16,
                       (iter > 0) || (ks > 0));
            TC_COMMIT(sb + A_MBO);
        }
    }

    MBAR_WAIT(sb + A_MBO, (NT - 1) & 1);
    TC_FENCE_AFTER();
    {
        float inv = 1.0f / l;
        float* dst = out + ((size_t)b * Ss + q0 + row) * DM + h * HD + half * 64;
#pragma unroll
        for (int cb = 0; cb < 2; cb++) {
            uint32_t og[32];
            TC_LD_X32(og, tw + TO_O + half * 64 + cb * 32);
            TC_WAIT_LD();
            float* of = (float*)og;
#pragma unroll
            for (int j = 0; j < 32; j += 4) {
                float4 o = make_float4(of[j] * inv, of[j + 1] * inv,
                                       of[j + 2] * inv, of[j + 3] * inv);
                *(float4*)(dst + cb * 32 + j) = o;
            }
        }
    }
    __syncthreads();
    if (wid == 0) TC_DEALLOC(tmem, 512);
#endif
}

// ---- Host ----
typedef CUresult (*PFN_encodeTiled)(CUtensorMap*, CUtensorMapDataType, cuuint32_t,
                                    void*, const cuuint64_t*, const cuuint64_t*,
                                    const cuuint32_t*, const cuuint32_t*,
                                    CUtensorMapInterleave, CUtensorMapSwizzle,
                                    CUtensorMapL2promotion, CUtensorMapFloatOOBfill);
static PFN_encodeTiled get_encoder() {
    static PFN_encodeTiled fn = nullptr;
    if (!fn) {
        cudaDriverEntryPointQueryResult qr;
        cudaGetDriverEntryPointByVersion("cuTensorMapEncodeTiled", (void**)&fn,
                                         12000, cudaEnableDefault, &qr);
    }
    return fn;
}
static void enc(CUtensorMap* m, void* base, int nd, uint64_t d0, uint64_t d1, uint64_t d2,
                uint32_t b0, uint32_t b1, CUtensorMapDataType dt) {
    cuuint64_t dims[3] = {d0, d1, d2};
    cuuint64_t strides[2] = {d0 * 2, d0 * d1 * 2};
    cuuint32_t box[3] = {b0, b1, 1};
    cuuint32_t es[3] = {1, 1, 1};
    get_encoder()(m, dt, nd, base, dims, strides, box, es,
                  CU_TENSOR_MAP_INTERLEAVE_NONE, CU_TENSOR_MAP_SWIZZLE_128B,
                  CU_TENSOR_MAP_L2_PROMOTION_L2_128B, CU_TENSOR_MAP_FLOAT_OOB_FILL_NONE);
}

extern "C" void kernel_launch(void* const* d_in, const int* in_sizes, int n_in,
                              void* d_out, int out_size) {
    const float* hs  = (const float*)d_in[0];
    const float* w   = (const float*)d_in[1];
    const float* bqv = (const float*)d_in[2];
    const float* wqn = (const float*)d_in[3];
    const float* wkn = (const float*)d_in[4];
    const float* cs  = (const float*)d_in[5];
    const float* sn  = (const float*)d_in[6];
    const int*   tsl = (const int*)d_in[7];
    float* out = (float*)d_out;

    __nv_bfloat16 *ah, *al, *wh, *wl, *kh, *kl;
    __half *vt;
    cudaGetSymbolAddress((void**)&ah, g_Ah);
    cudaGetSymbolAddress((void**)&al, g_Al);
    cudaGetSymbolAddress((void**)&wh, g_Wh);
    cudaGetSymbolAddress((void**)&wl, g_Wl);
    cudaGetSymbolAddress((void**)&kh, g_kh);
    cudaGetSymbolAddress((void**)&kl, g_kl);
    cudaGetSymbolAddress((void**)&vt, g_vt);

    CUtensorMap mAh, mAl, mWh, mWl, mKh, mKl, mVt;
    enc(&mAh, ah, 2, KD, MR, 1, 64, 128, CU_TENSOR_MAP_DATA_TYPE_BFLOAT16);
    enc(&mAl, al, 2, KD, MR, 1, 64, 128, CU_TENSOR_MAP_DATA_TYPE_BFLOAT16);
    enc(&mWh, wh, 2, KD, N3, 1, 64, 128, CU_TENSOR_MAP_DATA_TYPE_BFLOAT16);
    enc(&mWl, wl, 2, KD, N3, 1, 64, 128, CU_TENSOR_MAP_DATA_TYPE_BFLOAT16);
    enc(&mKh, kh, 3, HD, Ss, Bb * Hh, 64, 128, CU_TENSOR_MAP_DATA_TYPE_BFLOAT16);
    enc(&mKl, kl, 3, HD, Ss, Bb * Hh, 64, 128, CU_TENSOR_MAP_DATA_TYPE_BFLOAT16);
    enc(&mVt, vt, 3, Ss, HD, Bb * Hh, 64, 128, CU_TENSOR_MAP_DATA_TYPE_FLOAT16);

    int na4 = MR * KD / 4;
    int nw4 = N3 * KD / 4;
    int ntot = na4 + nw4;
    cvt_split2<<<(ntot + 255) / 256, 256>>>(hs, w, ah, al, wh, wl, na4, ntot);

    cudaFuncSetAttribute(qkv_gemm_tc, cudaFuncAttributeMaxDynamicSharedMemorySize, GEMM_SMEM);
    qkv_gemm_tc<<<dim3(MR / 128, N3 / 512), 256, GEMM_SMEM>>>(bqv, wqn, wkn, cs, sn, tsl,
                                                              mAh, mAl, mWh, mWl);

    v_transpose<<<dim3(Ss / 128, Bb * Hh), 256>>>();

    cudaFuncSetAttribute(attn, cudaFuncAttributeMaxDynamicSharedMemorySize, ATT_SMEM);
    attn<<<dim3(Ss / 128, Hh, Bb), 256, ATT_SMEM>>>(out, mKh, mKl, mVt);
}

// round 16
// speedup vs baseline: 1.1714x; 1.0462x over previous
#include <cuda_runtime.h>
#include <cuda.h>
#include <cuda_bf16.h>
#include <cuda_fp16.h>
#include <cstdint>

#if defined(__CUDA_ARCH_FEAT_SM103_ALL) || defined(__CUDA_ARCH_FEAT_SM100_ALL) || \
    (defined(__CUDA_ARCH_SPECIFIC__) && (__CUDA_ARCH_SPECIFIC__ >= 1000))
#define HAS_TCGEN05 1
#else
#define HAS_TCGEN05 0
#endif

#define Bb 2
#define Ss 2304
#define Hh 24
#define HD 128
#define DM 3072
#define N3 9216
#define KD 3072
#define MR (Bb*Ss)

__device__ alignas(128) __nv_bfloat16 g_Ah[(size_t)MR * KD];
__device__ alignas(128) __nv_bfloat16 g_Al[(size_t)MR * KD];
__device__ alignas(128) __nv_bfloat16 g_Wh[(size_t)N3 * KD];
__device__ alignas(128) __nv_bfloat16 g_Wl[(size_t)N3 * KD];
#define NBH ((size_t)Bb * Hh * Ss * HD)
__device__ alignas(128) __nv_bfloat16 g_qh[NBH];
__device__ alignas(128) __nv_bfloat16 g_ql[NBH];
__device__ alignas(128) __nv_bfloat16 g_kh[NBH];
__device__ alignas(128) __nv_bfloat16 g_kl[NBH];
__device__ alignas(128) __half g_vh[NBH];
__device__ alignas(128) __half g_vt[NBH];

__device__ __forceinline__ uint32_t smem_u32(const void* p) {
    uint32_t a;
    asm("{ .reg .u64 t; cvta.to.shared.u64 t, %1; cvt.u32.u64 %0, t; }" : "=r"(a) : "l"(p));
    return a;
}
__device__ __forceinline__ uint32_t h2_as_u32(__half2 h) {
    uint32_t u;
    asm("mov.b32 %0, %1;" : "=r"(u) : "r"(*(uint32_t*)&h));
    return u;
}
#define MK_DESC(addr) ((uint64_t(2) << 61) | (uint64_t(1) << 46) | (uint64_t(64) << 32) | \
                       (uint64_t(1) << 16) | ((uint64_t)((addr) >> 4) & 0x3FFF))
#define MBAR_INIT(m, c) asm volatile("mbarrier.init.shared.b64 [%0], %1;" :: "r"(m), "r"(c) : "memory")
#define MBAR_WAIT(m, p) asm volatile( \
    "{\n\t.reg .pred P1;\n\t" \
    "WL%=:\n\tmbarrier.try_wait.parity.acquire.cta.shared::cta.b64 P1, [%0], %1, 0x989680;\n\t" \
    "@P1 bra.uni WD%=;\n\tbra.uni WL%=;\n\tWD%=:\n\t}" \
    :: "r"(m), "r"(p) : "memory")
#define MBAR_EXPECT_TX(m, n) asm volatile( \
    "mbarrier.arrive.expect_tx.shared.b64 _, [%0], %1;" :: "r"(m), "r"(n) : "memory")
#define TMA_3D(dst, map, x, y, z, mb) asm volatile( \
    "cp.async.bulk.tensor.3d.shared::cta.global.tile.mbarrier::complete_tx::bytes " \
    "[%0], [%1, {%2, %3, %4}], [%5];" \
    :: "r"(dst), "l"(map), "r"(x), "r"(y), "r"(z), "r"(mb) : "memory")
#define TMA_2D_CG2(dst, map, x, y, mb) asm volatile( \
    "{\n\t.reg .b32 lb;\n\tand.b32 lb, %4, 0xFEFFFFFF;\n\t" \
    "cp.async.bulk.tensor.2d.cta_group::2.shared::cluster.global.tile." \
    "mbarrier::complete_tx::bytes [%0], [%1, {%2, %3}], [lb];\n\t}" \
    :: "r"(dst), "l"(map), "r"(x), "r"(y), "r"(mb) : "memory")
#define CLUSTER_SYNC() do { \
    asm volatile("barrier.cluster.arrive.aligned;" ::: "memory"); \
    asm volatile("barrier.cluster.wait.aligned;" ::: "memory"); } while (0)

#if HAS_TCGEN05
__device__ __forceinline__ void mma_ss_cg2(uint32_t d, uint64_t a, uint64_t b,
                                           uint32_t idesc, uint32_t en) {
    asm volatile(
        "{\n\t.reg .pred p;\n\tsetp.ne.u32 p, %4, 0;\n\t"
        "tcgen05.mma.cta_group::2.kind::f16 [%0], %1, %2, %3, "
        "{%5, %5, %5, %5, %5, %5, %5, %5}, p;\n\t}"
        :: "r"(d), "l"(a), "l"(b), "r"(idesc), "r"(en), "r"(0u) : "memory");
}
__device__ __forceinline__ void mma_ts(uint32_t d, uint32_t a, uint64_t b,
                                       uint32_t idesc, uint32_t en) {
    asm volatile(
        "{\n\t.reg .pred p;\n\tsetp.ne.u32 p, %4, 0;\n\t"
        "tcgen05.mma.cta_group::1.kind::f16 [%0], [%1], %2, %3, {%5, %5, %5, %5}, p;\n\t}"
        :: "r"(d), "r"(a), "l"(b), "r"(idesc), "r"(en), "r"(0u) : "memory");
}
#define TC_COMMIT(m) asm volatile( \
    "tcgen05.commit.cta_group::1.mbarrier::arrive::one.shared::cluster.b64 [%0];" :: "r"(m) : "memory")
#define TC_COMMIT_MC2(m) asm volatile( \
    "tcgen05.commit.cta_group::2.mbarrier::arrive::one.shared::cluster.multicast::cluster.b64 [%0], %1;" \
    :: "r"(m), "h"((uint16_t)0x3) : "memory")
#define TC_ALLOC(sm, n)  asm volatile("tcgen05.alloc.cta_group::1.sync.aligned.shared::cta.b32 [%0], %1;" :: "r"(sm), "r"(n) : "memory")
#define TC_DEALLOC(t, n) asm volatile("tcgen05.dealloc.cta_group::1.sync.aligned.b32 %0, %1;" :: "r"(t), "r"(n))
#define TC_ALLOC_CG2(sm, n)  asm volatile("tcgen05.alloc.cta_group::2.sync.aligned.shared::cta.b32 [%0], %1;" :: "r"(sm), "r"(n) : "memory")
#define TC_DEALLOC_CG2(t, n) asm volatile("tcgen05.dealloc.cta_group::2.sync.aligned.b32 %0, %1;" :: "r"(t), "r"(n))
#define TC_RELINQ_CG2() asm volatile("tcgen05.relinquish_alloc_permit.cta_group::2.sync.aligned;")
#define TC_FENCE_AFTER() asm volatile("tcgen05.fence::after_thread_sync;" ::: "memory")
#define TC_FENCE_BEFORE() asm volatile("tcgen05.fence::before_thread_sync;" ::: "memory")
#define TC_WAIT_LD()     asm volatile("tcgen05.wait::ld.sync.aligned;" ::: "memory")
#define TC_WAIT_ST()     asm volatile("tcgen05.wait::st.sync.aligned;" ::: "memory")
#define FENCE_ASYNC()    asm volatile("fence.proxy.async.shared::cta;" ::: "memory")

#define TC_LD_X32(r, a) asm volatile( \
    "tcgen05.ld.sync.aligned.32x32b.x32.b32 " \
    "{%0, %1, %2, %3, %4, %5, %6, %7, %8, %9, %10, %11, %12, %13, %14, %15, " \
    "%16, %17, %18, %19, %20, %21, %22, %23, %24, %25, %26, %27, %28, %29, %30, %31}, [%32];" \
    : "=r"((r)[0]), "=r"((r)[1]), "=r"((r)[2]), "=r"((r)[3]), "=r"((r)[4]), "=r"((r)[5]), \
      "=r"((r)[6]), "=r"((r)[7]), "=r"((r)[8]), "=r"((r)[9]), "=r"((r)[10]), "=r"((r)[11]), \
      "=r"((r)[12]), "=r"((r)[13]), "=r"((r)[14]), "=r"((r)[15]), "=r"((r)[16]), "=r"((r)[17]), \
      "=r"((r)[18]), "=r"((r)[19]), "=r"((r)[20]), "=r"((r)[21]), "=r"((r)[22]), "=r"((r)[23]), \
      "=r"((r)[24]), "=r"((r)[25]), "=r"((r)[26]), "=r"((r)[27]), "=r"((r)[28]), "=r"((r)[29]), \
      "=r"((r)[30]), "=r"((r)[31]) : "r"(a))

#define TC_ST_X32(a, r) asm volatile( \
    "tcgen05.st.sync.aligned.32x32b.x32.b32 [%0], " \
    "{%1, %2, %3, %4, %5, %6, %7, %8, %9, %10, %11, %12, %13, %14, %15, %16, " \
    "%17, %18, %19, %20, %21, %22, %23, %24, %25, %26, %27, %28, %29, %30, %31, %32};" \
    :: "r"(a), \
       "r"((r)[0]), "r"((r)[1]), "r"((r)[2]), "r"((r)[3]), "r"((r)[4]), "r"((r)[5]), \
       "r"((r)[6]), "r"((r)[7]), "r"((r)[8]), "r"((r)[9]), "r"((r)[10]), "r"((r)[11]), \
       "r"((r)[12]), "r"((r)[13]), "r"((r)[14]), "r"((r)[15]), "r"((r)[16]), "r"((r)[17]), \
       "r"((r)[18]), "r"((r)[19]), "r"((r)[20]), "r"((r)[21]), "r"((r)[22]), "r"((r)[23]), \
       "r"((r)[24]), "r"((r)[25]), "r"((r)[26]), "r"((r)[27]), "r"((r)[28]), "r"((r)[29]), \
       "r"((r)[30]), "r"((r)[31]) : "memory")
#endif

// ---- Kernel 0: fused fp32 -> (hi,lo) bf16 ----
__global__ __launch_bounds__(256) void cvt_split2(const float* __restrict__ a,
                                                  const float* __restrict__ w,
                                                  __nv_bfloat16* __restrict__ ah,
                                                  __nv_bfloat16* __restrict__ al,
                                                  __nv_bfloat16* __restrict__ wh,
                                                  __nv_bfloat16* __restrict__ wl,
                                                  int na4, int ntot) {
    int i = blockIdx.x * 256 + threadIdx.x;
    if (i >= ntot) return;
    const float* x; __nv_bfloat16 *hi, *lo; int j;
    if (i < na4) { x = a; hi = ah; lo = al; j = i; }
    else         { x = w; hi = wh; lo = wl; j = i - na4; }
    float4 v = ((const float4*)x)[j];
    __nv_bfloat16 h0 = __float2bfloat16(v.x), h1 = __float2bfloat16(v.y);
    __nv_bfloat16 h2 = __float2bfloat16(v.z), h3 = __float2bfloat16(v.w);
    __nv_bfloat16 l0 = __float2bfloat16(v.x - __bfloat162float(h0));
    __nv_bfloat16 l1 = __float2bfloat16(v.y - __bfloat162float(h1));
    __nv_bfloat16 l2 = __float2bfloat16(v.z - __bfloat162float(h2));
    __nv_bfloat16 l3 = __float2bfloat16(v.w - __bfloat162float(h3));
    ((__nv_bfloat162*)hi)[2 * j] = __nv_bfloat162(h0, h1);
    ((__nv_bfloat162*)hi)[2 * j + 1] = __nv_bfloat162(h2, h3);
    ((__nv_bfloat162*)lo)[2 * j] = __nv_bfloat162(l0, l1);
    ((__nv_bfloat162*)lo)[2 * j + 1] = __nv_bfloat162(l2, l3);
}

// ---- Kernel 1: cg2 GEMM, 256x512 pair tile, fused epilogue (unchanged R15) ----
#define GS_AH 0
#define GS_AL 16384
#define GS_W0H 32768
#define GS_W0L 49152
#define GS_W1H 65536
#define GS_W1L 81920
#define G_STG 98304
#define SM_BIAS  196608
#define SM_TMEMP 198656
#define SM_MB    198664
#define SM_KF    198680
#define GEMM_SMEM 198784
#define IDESC_CG2N256 0x10400490u
#define IDESC_BF16 0x8200490u
#define IDESC_FP16 0x8200010u
#define NCH 48

extern __shared__ float smf[];

__global__ __launch_bounds__(256) __cluster_dims__(2, 1, 1)
void qkv_gemm_tc(const float* __restrict__ bias,
                 const float* __restrict__ wq, const float* __restrict__ wk,
                 const float* __restrict__ cs, const float* __restrict__ sn,
                 const int* __restrict__ tsl,
                 const __grid_constant__ CUtensorMap mAh,
                 const __grid_constant__ CUtensorMap mAl,
                 const __grid_constant__ CUtensorMap mWh,
                 const __grid_constant__ CUtensorMap mWl) {
#if HAS_TCGEN05
    char* sm = (char*)smf;
    uint32_t sb = smem_u32(sm);
    int t = threadIdx.x;
    int wid = t >> 5;
    int rank = blockIdx.x & 1;
    int m0 = (blockIdx.x >> 1) * 256 + rank * 128;
    int n0 = blockIdx.y * 512;

    if (wid == 0) TC_ALLOC_CG2(sb + SM_TMEMP, 512);
    if (t == 0) {
        MBAR_INIT(sb + SM_MB + 0, 1);
        MBAR_INIT(sb + SM_MB + 8, 1);
        MBAR_INIT(sb + SM_KF + 0, 1);
        MBAR_INIT(sb + SM_KF + 8, 1);
        FENCE_ASYNC();
        if (rank == 0) {
            MBAR_EXPECT_TX(sb + SM_KF + 0, 196608u);
            MBAR_EXPECT_TX(sb + SM_KF + 8, 196608u);
        }
    }
    ((float*)(sm + SM_BIAS))[t] = bias[n0 + t];
    ((float*)(sm + SM_BIAS))[t + 256] = bias[n0 + t + 256];
    __syncthreads();
    CLUSTER_SYNC();
    uint32_t tmem;
    asm volatile("ld.shared.b32 %0, [%1];" : "=r"(tmem) : "r"(sb + SM_TMEMP));

    if (t == 0) {
#pragma unroll
        for (int c = 0; c < 2; c++) {
            uint32_t stg = sb + c * G_STG, kfb = sb + SM_KF + c * 8;
            int k0 = c * 64;
            TMA_2D_CG2(stg + GS_AH,  &mAh, k0, m0, kfb);
            TMA_2D_CG2(stg + GS_AL,  &mAl, k0, m0, kfb);
            TMA_2D_CG2(stg + GS_W0H, &mWh, k0, n0 + rank * 128, kfb);
            TMA_2D_CG2(stg + GS_W0L, &mWl, k0, n0 + rank * 128, kfb);
            TMA_2D_CG2(stg + GS_W1H, &mWh, k0, n0 + 256 + rank * 128, kfb);
            TMA_2D_CG2(stg + GS_W1L, &mWl, k0, n0 + 256 + rank * 128, kfb);
        }
        const int ca[3] = {0, 0, 1}, cw[3] = {0, 1, 0};
        for (int i = 0; i < NCH; i++) {
            int s = i & 1;
            if (rank == 0) {
                MBAR_WAIT(sb + SM_KF + s * 8, (i >> 1) & 1);
                if (i + 2 < NCH) MBAR_EXPECT_TX(sb + SM_KF + s * 8, 196608u);
                uint32_t stg = sb + s * G_STG;
                uint64_t dA[2]  = {MK_DESC(stg + GS_AH), MK_DESC(stg + GS_AL)};
                uint64_t dW0[2] = {MK_DESC(stg + GS_W0H), MK_DESC(stg + GS_W0L)};
                uint64_t dW1[2] = {MK_DESC(stg + GS_W1H), MK_DESC(stg + GS_W1L)};
#pragma unroll
                for (int c3 = 0; c3 < 3; c3++) {
                    uint64_t b0 = cw[c3] ? dW0[1] : dW0[0];
                    uint64_t b1 = cw[c3] ? dW1[1] : dW1[0];
                    uint64_t aa = dA[ca[c3]];
#pragma unroll
                    for (int ks = 0; ks < 4; ks++) {
                        uint32_t en = (i | c3 | ks) ? 1u : 0u;
                        mma_ss_cg2(tmem,       aa + ks * 2, b0 + ks * 2, IDESC_CG2N256, en);
                        mma_ss_cg2(tmem + 256, aa + ks * 2, b1 + ks * 2, IDESC_CG2N256, en);
                    }
                }
                TC_COMMIT_MC2(sb + SM_MB + s * 8);
            }
            if (i >= 1 && i + 1 < NCH) {
                int s2 = (i + 1) & 1;
                MBAR_WAIT(sb + SM_MB + s2 * 8, ((i - 1) >> 1) & 1);
                uint32_t stg = sb + s2 * G_STG, kfb = sb + SM_KF + s2 * 8;
                int k0 = (i + 1) * 64;
                TMA_2D_CG2(stg + GS_AH,  &mAh, k0, m0, kfb);
                TMA_2D_CG2(stg + GS_AL,  &mAl, k0, m0, kfb);
                TMA_2D_CG2(stg + GS_W0H, &mWh, k0, n0 + rank * 128, kfb);
                TMA_2D_CG2(stg + GS_W0L, &mWl, k0, n0 + rank * 128, kfb);
                TMA_2D_CG2(stg + GS_W1H, &mWh, k0, n0 + 256 + rank * 128, kfb);
                TMA_2D_CG2(stg + GS_W1L, &mWl, k0, n0 + 256 + rank * 128, kfb);
            }
        }
        MBAR_WAIT(sb + SM_MB + 0, 1);
        MBAR_WAIT(sb + SM_MB + 8, 1);
    }
    __syncthreads();
    TC_FENCE_AFTER();

    {
        int r = t & 127;
        int m = m0 + r;
        int b = m / Ss, s2 = m % Ss;
        int sec = n0 / DM;
        int h0 = (n0 % DM) / HD;
        uint32_t tw = tmem + ((uint32_t)(wid & 3) << 21);
        int T = tsl[0];
        bool rope = (s2 >= T);
        int p = s2 - T;
#pragma unroll
        for (int hc2 = 0; hc2 < 2; hc2++) {
            int hc = (t >> 7) + hc2 * 2;
            uint32_t cbase = tw + hc * 128;
            const float* bs = (const float*)(sm + SM_BIAS) + hc * 128;
            size_t obase = ((size_t)(b * Hh + h0 + hc) * Ss + s2) * (size_t)HD;

            if (sec == 2) {
                __half* dv = g_vh + obase;
#pragma unroll
                for (int cb = 0; cb < 4; cb++) {
                    uint32_t rg[32];
                    TC_LD_X32(rg, cbase + cb * 32);
                    TC_WAIT_LD();
                    __half hb[32];
#pragma unroll
                    for (int j = 0; j < 32; j += 2) {
                        float a0 = __uint_as_float(rg[j]) + bs[cb * 32 + j];
                        float a1 = __uint_as_float(rg[j + 1]) + bs[cb * 32 + j + 1];
                        *(__half2*)(hb + j) = __float22half2_rn(make_float2(a0, a1));
                    }
#pragma unroll
                    for (int q4 = 0; q4 < 4; q4++)
                        *(uint4*)(dv + cb * 32 + q4 * 8) = *(uint4*)(hb + q4 * 8);
                }
            } else {
                const float* wn = (sec == 0) ? wq : wk;
                float ssq = 0.0f;
#pragma unroll
                for (int cb = 0; cb < 4; cb++) {
                    uint32_t rg[32];
                    TC_LD_X32(rg, cbase + cb * 32);
                    TC_WAIT_LD();
#pragma unroll
                    for (int j = 0; j < 32; j++) {
                        float a = __uint_as_float(rg[j]) + bs[cb * 32 + j];
                        ssq += a * a;
                    }
                }
                float rms = rsqrtf(ssq * (1.0f / 128.0f) + 1e-6f);
                // qscale = (1/sqrt(128)) * log2(e): attention uses exp2
                float qscale = (sec == 0) ? 0.12752050778924437f : 1.0f;
                __nv_bfloat16* dh = ((sec == 0) ? g_qh : g_kh) + obase;
                __nv_bfloat16* dl = ((sec == 0) ? g_ql : g_kl) + obase;
#pragma unroll
                for (int cb = 0; cb < 4; cb++) {
                    uint32_t rg[32];
                    TC_LD_X32(rg, cbase + cb * 32);
                    TC_WAIT_LD();
                    float y[32];
#pragma unroll
                    for (int j = 0; j < 32; j++)
                        y[j] = (__uint_as_float(rg[j]) + bs[cb * 32 + j]) * rms * wn[cb * 32 + j];
                    if (rope) {
#pragma unroll
                        for (int jj = 0; jj < 16; jj++) {
                            float c = cs[p * 64 + cb * 16 + jj], sv = sn[p * 64 + cb * 16 + jj];
                            float x1 = y[2 * jj], x2 = y[2 * jj + 1];
                            y[2 * jj] = x1 * c - x2 * sv;
                            y[2 * jj + 1] = x2 * c + x1 * sv;
                        }
                    }
                    __nv_bfloat16 hb[32], lb[32];
#pragma unroll
                    for (int j = 0; j < 32; j++) {
                        float v = y[j] * qscale;
                        __nv_bfloat16 hv = __float2bfloat16(v);
                        hb[j] = hv;
                        lb[j] = __float2bfloat16(v - __bfloat162float(hv));
                    }
#pragma unroll
                    for (int q4 = 0; q4 < 4; q4++) {
                        *(uint4*)(dh + cb * 32 + q4 * 8) = *(uint4*)(hb + q4 * 8);
                        *(uint4*)(dl + cb * 32 + q4 * 8) = *(uint4*)(lb + q4 * 8);
                    }
                }
            }
        }
    }
    __syncthreads();
    if (wid == 0) { TC_RELINQ_CG2(); TC_DEALLOC_CG2(tmem, 512); }
    CLUSTER_SYNC();
#endif
}

// ---- Kernel 2b: V transpose ----
__global__ __launch_bounds__(256) void v_transpose() {
    __shared__ __half ts[128 * 129];
    int t = threadIdx.x;
    int s0 = blockIdx.x * 128;
    int bh = blockIdx.y;
    const __half* src = g_vh + ((size_t)bh * Ss + s0) * HD;
#pragma unroll
    for (int i = 0; i < 8; i++) {
        int idx = t + i * 256;
        int s = idx >> 4, c8 = idx & 15;
        uint4 v = *(const uint4*)(src + s * HD + c8 * 8);
        __half tmp[8];
        *(uint4*)tmp = v;
#pragma unroll
        for (int j = 0; j < 8; j++) ts[s * 129 + c8 * 8 + j] = tmp[j];
    }
    __syncthreads();
    __half* dst = g_vt + (size_t)bh * HD * Ss;
#pragma unroll
    for (int i = 0; i < 8; i++) {
        int idx = t + i * 256;
        int d = idx >> 4, s8 = idx & 15;
        __half o[8];
#pragma unroll
        for (int j = 0; j < 8; j++) o[j] = ts[(s8 * 8 + j) * 129 + d];
        *(uint4*)(dst + (size_t)d * Ss + s0 + s8 * 8) = *(uint4*)o;
    }
}

// ---- Kernel 3: attention — R15 structure, 2-term QK (Kl dropped) ----
#define A_STG 65536
#define AS_KH 0
#define AS_V  32768
#define A_SMAX 131072
#define A_SSUM 132096
#define A_PTR  133120
#define A_MBS  133128
#define A_MBO  133136
#define A_KF   133144
#define ATT_SMEM 133248
#define NT 18
#define TO_O  0
#define TO_S  128
#define TO_P  256
#define TO_QH 320
#define TO_QL 384

__device__ __forceinline__ uint32_t dstep(int ks) {
    return (uint32_t)((ks >> 2) * 1024 + (ks & 3) * 2);
}

__global__ __launch_bounds__(256, 1) void attn(
        float* __restrict__ out,
        const __grid_constant__ CUtensorMap mKh,
        const __grid_constant__ CUtensorMap mVt) {
#if HAS_TCGEN05
    char* sm = (char*)smf;
    uint32_t sb = smem_u32(sm);
    int t = threadIdx.x;
    int wid = t >> 5;
    int row = t & 127;
    int half = t >> 7;
    int q0 = blockIdx.x * 128;
    int h = blockIdx.y, b = blockIdx.z;
    int bh = b * Hh + h;

    if (wid == 0) TC_ALLOC(sb + A_PTR, 512);
    if (t == 0) {
        MBAR_INIT(sb + A_MBS, 1);
        MBAR_INIT(sb + A_MBO, 1);
        MBAR_INIT(sb + A_KF + 0, 1);
        MBAR_INIT(sb + A_KF + 8, 1);
        FENCE_ASYNC();
        MBAR_EXPECT_TX(sb + A_KF, 65536u);
        TMA_3D(sb + AS_KH,         &mKh, 0,  0, bh, sb + A_KF);
        TMA_3D(sb + AS_KH + 16384, &mKh, 64, 0, bh, sb + A_KF);
        TMA_3D(sb + AS_V,          &mVt, 0,  0, bh, sb + A_KF);
        TMA_3D(sb + AS_V + 16384,  &mVt, 64, 0, bh, sb + A_KF);
    }
    __syncthreads();
    uint32_t tmem;
    asm volatile("ld.shared.b32 %0, [%1];" : "=r"(tmem) : "r"(sb + A_PTR));
    uint32_t tw = tmem + ((uint32_t)(wid & 3) << 21);

    {
        const uint4* qsrc = (const uint4*)((half == 0 ? g_qh : g_ql) +
                                ((size_t)bh * Ss + q0 + row) * HD);
        uint32_t dstc = (half == 0) ? (tw + TO_QH) : (tw + TO_QL);
        uint32_t rg[32];
#pragma unroll
        for (int hb = 0; hb < 2; hb++) {
#pragma unroll
            for (int j = 0; j < 8; j++) ((uint4*)rg)[j] = qsrc[hb * 8 + j];
            TC_ST_X32(dstc + hb * 32, rg);
        }
        TC_WAIT_ST();
    }
    TC_FENCE_BEFORE();
    __syncthreads();

    float m_ref = -1e30f, l = 0.0f;

    for (int iter = 0; iter < NT; iter++) {
        int s = iter & 1;
        uint32_t stg = sb + s * A_STG;

        // S-MMA: 2-term  S = Qh*Kh + Ql*Kh
        if (t == 0) {
            TC_FENCE_AFTER();
            MBAR_WAIT(sb + A_KF + s * 8, (iter >> 1) & 1);
            uint64_t dKh = MK_DESC(stg + AS_KH);
#pragma unroll
            for (int ks = 0; ks < 8; ks++)
                mma_ts(tmem + TO_S, tmem + TO_QH + ks * 8, dKh + dstep(ks), IDESC_BF16, ks > 0);
#pragma unroll
            for (int ks = 0; ks < 8; ks++)
                mma_ts(tmem + TO_S, tmem + TO_QL + ks * 8, dKh + dstep(ks), IDESC_BF16, 1);
            TC_COMMIT(sb + A_MBS);
        }

        if (iter > 0) MBAR_WAIT(sb + A_MBO, (iter - 1) & 1);

        if (t == 0 && iter + 1 < NT) {
            int s2 = (iter + 1) & 1;
            uint32_t st2 = sb + s2 * A_STG;
            int kt = (iter + 1) * 128;
            MBAR_EXPECT_TX(sb + A_KF + s2 * 8, 65536u);
            TMA_3D(st2 + AS_KH,         &mKh, 0,  kt, bh, sb + A_KF + s2 * 8);
            TMA_3D(st2 + AS_KH + 16384, &mKh, 64, kt, bh, sb + A_KF + s2 * 8);
            TMA_3D(st2 + AS_V,          &mVt, kt,      0, bh, sb + A_KF + s2 * 8);
            TMA_3D(st2 + AS_V + 16384,  &mVt, kt + 64, 0, bh, sb + A_KF + s2 * 8);
        }

        // softmax in exp2 domain
        {
            MBAR_WAIT(sb + A_MBS, iter & 1);
            TC_FENCE_AFTER();
            float sc[64];
            uint32_t* scu = (uint32_t*)sc;
            uint32_t scol = tw + TO_S + half * 64;
            TC_LD_X32(scu + 0,  scol + 0);
            TC_LD_X32(scu + 32, scol + 32);
            TC_WAIT_LD();
            float pmax = sc[0];
#pragma unroll
            for (int c = 1; c < 64; c++) pmax = fmaxf(pmax, sc[c]);
            ((float*)(sm + A_SMAX))[t] = pmax;
            __syncthreads();
            float tmax = fmaxf(pmax, ((float*)(sm + A_SMAX))[t ^ 128]);
            bool need = tmax > m_ref + 6.0f;
            float alpha = 1.0f;
            if (need) { alpha = exp2f(m_ref - tmax); m_ref = tmax; }
            float psum = 0.0f;
            uint32_t pr[32];
#pragma unroll
            for (int c = 0; c < 32; c++) {
                float p0 = exp2f(sc[2 * c] - m_ref);
                float p1 = exp2f(sc[2 * c + 1] - m_ref);
                psum += p0 + p1;
                pr[c] = h2_as_u32(__float22half2_rn(make_float2(p0, p1)));
            }
            ((float*)(sm + A_SSUM))[t] = psum;
            TC_ST_X32(tw + TO_P + half * 32, pr);
            if (iter > 0 && __any_sync(0xffffffffu, need)) {
#pragma unroll
                for (int cb = 0; cb < 2; cb++) {
                    uint32_t og[32];
                    TC_LD_X32(og, tw + TO_O + half * 64 + cb * 32);
                    TC_WAIT_LD();
                    float* of = (float*)og;
#pragma unroll
                    for (int j = 0; j < 32; j++) of[j] *= alpha;
                    TC_ST_X32(tw + TO_O + half * 64 + cb * 32, og);
                }
            }
            TC_WAIT_ST();
            TC_FENCE_BEFORE();
            __syncthreads();
            l = l * alpha + psum + ((float*)(sm + A_SSUM))[t ^ 128];
        }

        if (t == 0) {
            TC_FENCE_AFTER();
            uint64_t dV = MK_DESC(stg + AS_V);
#pragma unroll
            for (int ks = 0; ks < 8; ks++)
                mma_ts(tmem + TO_O, tmem + TO_P + ks * 8, dV + dstep(ks), IDESC_FP16,
                       (iter > 0) || (ks > 0));
            TC_COMMIT(sb + A_MBO);
        }
    }

    MBAR_WAIT(sb + A_MBO, (NT - 1) & 1);
    TC_FENCE_AFTER();
    {
        float inv = 1.0f / l;
        float* dst = out + ((size_t)b * Ss + q0 + row) * DM + h * HD + half * 64;
#pragma unroll
        for (int cb = 0; cb < 2; cb++) {
            uint32_t og[32];
            TC_LD_X32(og, tw + TO_O + half * 64 + cb * 32);
            TC_WAIT_LD();
            float* of = (float*)og;
#pragma unroll
            for (int j = 0; j < 32; j += 4) {
                float4 o = make_float4(of[j] * inv, of[j + 1] * inv,
                                       of[j + 2] * inv, of[j + 3] * inv);
                *(float4*)(dst + cb * 32 + j) = o;
            }
        }
    }
    __syncthreads();
    if (wid == 0) TC_DEALLOC(tmem, 512);
#endif
}

// ---- Host ----
typedef CUresult (*PFN_encodeTiled)(CUtensorMap*, CUtensorMapDataType, cuuint32_t,
                                    void*, const cuuint64_t*, const cuuint64_t*,
                                    const cuuint32_t*, const cuuint32_t*,
                                    CUtensorMapInterleave, CUtensorMapSwizzle,
                                    CUtensorMapL2promotion, CUtensorMapFloatOOBfill);
static PFN_encodeTiled get_encoder() {
    static PFN_encodeTiled fn = nullptr;
    if (!fn) {
        cudaDriverEntryPointQueryResult qr;
        cudaGetDriverEntryPointByVersion("cuTensorMapEncodeTiled", (void**)&fn,
                                         12000, cudaEnableDefault, &qr);
    }
    return fn;
}
static void enc(CUtensorMap* m, void* base, int nd, uint64_t d0, uint64_t d1, uint64_t d2,
                uint32_t b0, uint32_t b1, CUtensorMapDataType dt) {
    cuuint64_t dims[3] = {d0, d1, d2};
    cuuint64_t strides[2] = {d0 * 2, d0 * d1 * 2};
    cuuint32_t box[3] = {b0, b1, 1};
    cuuint32_t es[3] = {1, 1, 1};
    get_encoder()(m, dt, nd, base, dims, strides, box, es,
                  CU_TENSOR_MAP_INTERLEAVE_NONE, CU_TENSOR_MAP_SWIZZLE_128B,
                  CU_TENSOR_MAP_L2_PROMOTION_L2_128B, CU_TENSOR_MAP_FLOAT_OOB_FILL_NONE);
}

extern "C" void kernel_launch(void* const* d_in, const int* in_sizes, int n_in,
                              void* d_out, int out_size) {
    const float* hs  = (const float*)d_in[0];
    const float* w   = (const float*)d_in[1];
    const float* bqv = (const float*)d_in[2];
    const float* wqn = (const float*)d_in[3];
    const float* wkn = (const float*)d_in[4];
    const float* cs  = (const float*)d_in[5];
    const float* sn  = (const float*)d_in[6];
    const int*   tsl = (const int*)d_in[7];
    float* out = (float*)d_out;

    __nv_bfloat16 *ah, *al, *wh, *wl, *kh;
    __half *vt;
    cudaGetSymbolAddress((void**)&ah, g_Ah);
    cudaGetSymbolAddress((void**)&al, g_Al);
    cudaGetSymbolAddress((void**)&wh, g_Wh);
    cudaGetSymbolAddress((void**)&wl, g_Wl);
    cudaGetSymbolAddress((void**)&kh, g_kh);
    cudaGetSymbolAddress((void**)&vt, g_vt);

    CUtensorMap mAh, mAl, mWh, mWl, mKh, mVt;
    enc(&mAh, ah, 2, KD, MR, 1, 64, 128, CU_TENSOR_MAP_DATA_TYPE_BFLOAT16);
    enc(&mAl, al, 2, KD, MR, 1, 64, 128, CU_TENSOR_MAP_DATA_TYPE_BFLOAT16);
    enc(&mWh, wh, 2, KD, N3, 1, 64, 128, CU_TENSOR_MAP_DATA_TYPE_BFLOAT16);
    enc(&mWl, wl, 2, KD, N3, 1, 64, 128, CU_TENSOR_MAP_DATA_TYPE_BFLOAT16);
    enc(&mKh, kh, 3, HD, Ss, Bb * Hh, 64, 128, CU_TENSOR_MAP_DATA_TYPE_BFLOAT16);
    enc(&mVt, vt, 3, Ss, HD, Bb * Hh, 64, 128, CU_TENSOR_MAP_DATA_TYPE_FLOAT16);

    int na4 = MR * KD / 4;
    int nw4 = N3 * KD / 4;
    int ntot = na4 + nw4;
    cvt_split2<<<(ntot + 255) / 256, 256>>>(hs, w, ah, al, wh, wl, na4, ntot);

    cudaFuncSetAttribute(qkv_gemm_tc, cudaFuncAttributeMaxDynamicSharedMemorySize, GEMM_SMEM);
    qkv_gemm_tc<<<dim3(MR / 128, N3 / 512), 256, GEMM_SMEM>>>(bqv, wqn, wkn, cs, sn, tsl,
                                                              mAh, mAl, mWh, mWl);

    v_transpose<<<dim3(Ss / 128, Bb * Hh), 256>>>();

    cudaFuncSetAttribute(attn, cudaFuncAttributeMaxDynamicSharedMemorySize, ATT_SMEM);
    attn<<<dim3(Ss / 128, Hh, Bb), 256, ATT_SMEM>>>(out, mKh, mVt);
}

// round 17
// speedup vs baseline: 1.2314x; 1.0512x over previous
#include <cuda_runtime.h>
#include <cuda.h>
#include <cuda_bf16.h>
#include <cuda_fp16.h>
#include <cstdint>

#if defined(__CUDA_ARCH_FEAT_SM103_ALL) || defined(__CUDA_ARCH_FEAT_SM100_ALL) || \
    (defined(__CUDA_ARCH_SPECIFIC__) && (__CUDA_ARCH_SPECIFIC__ >= 1000))
#define HAS_TCGEN05 1
#else
#define HAS_TCGEN05 0
#endif

#define Bb 2
#define Ss 2304
#define Hh 24
#define HD 128
#define DM 3072
#define N3 9216
#define KD 3072
#define MR (Bb*Ss)

__device__ alignas(128) __nv_bfloat16 g_Ah[(size_t)MR * KD];
__device__ alignas(128) __nv_bfloat16 g_Al[(size_t)MR * KD];
__device__ alignas(128) __nv_bfloat16 g_Wh[(size_t)N3 * KD];
__device__ alignas(128) __nv_bfloat16 g_Wl[(size_t)N3 * KD];
#define NBH ((size_t)Bb * Hh * Ss * HD)
__device__ alignas(128) __half g_qf[NBH];   // fp16 Q (scaled by log2e/sqrt(128))
__device__ alignas(128) __half g_kf[NBH];   // fp16 K
__device__ alignas(128) __half g_vh[NBH];
__device__ alignas(128) __half g_vt[NBH];

__device__ __forceinline__ uint32_t smem_u32(const void* p) {
    uint32_t a;
    asm("{ .reg .u64 t; cvta.to.shared.u64 t, %1; cvt.u32.u64 %0, t; }" : "=r"(a) : "l"(p));
    return a;
}
__device__ __forceinline__ uint32_t h2_as_u32(__half2 h) {
    uint32_t u;
    asm("mov.b32 %0, %1;" : "=r"(u) : "r"(*(uint32_t*)&h));
    return u;
}
#define MK_DESC(addr) ((uint64_t(2) << 61) | (uint64_t(1) << 46) | (uint64_t(64) << 32) | \
                       (uint64_t(1) << 16) | ((uint64_t)((addr) >> 4) & 0x3FFF))
#define MBAR_INIT(m, c) asm volatile("mbarrier.init.shared.b64 [%0], %1;" :: "r"(m), "r"(c) : "memory")
#define MBAR_WAIT(m, p) asm volatile( \
    "{\n\t.reg .pred P1;\n\t" \
    "WL%=:\n\tmbarrier.try_wait.parity.acquire.cta.shared::cta.b64 P1, [%0], %1, 0x989680;\n\t" \
    "@P1 bra.uni WD%=;\n\tbra.uni WL%=;\n\tWD%=:\n\t}" \
    :: "r"(m), "r"(p) : "memory")
#define MBAR_EXPECT_TX(m, n) asm volatile( \
    "mbarrier.arrive.expect_tx.shared.b64 _, [%0], %1;" :: "r"(m), "r"(n) : "memory")
#define TMA_3D(dst, map, x, y, z, mb) asm volatile( \
    "cp.async.bulk.tensor.3d.shared::cta.global.tile.mbarrier::complete_tx::bytes " \
    "[%0], [%1, {%2, %3, %4}], [%5];" \
    :: "r"(dst), "l"(map), "r"(x), "r"(y), "r"(z), "r"(mb) : "memory")
#define TMA_2D_CG2(dst, map, x, y, mb) asm volatile( \
    "{\n\t.reg .b32 lb;\n\tand.b32 lb, %4, 0xFEFFFFFF;\n\t" \
    "cp.async.bulk.tensor.2d.cta_group::2.shared::cluster.global.tile." \
    "mbarrier::complete_tx::bytes [%0], [%1, {%2, %3}], [lb];\n\t}" \
    :: "r"(dst), "l"(map), "r"(x), "r"(y), "r"(mb) : "memory")
#define CLUSTER_SYNC() do { \
    asm volatile("barrier.cluster.arrive.aligned;" ::: "memory"); \
    asm volatile("barrier.cluster.wait.aligned;" ::: "memory"); } while (0)

#if HAS_TCGEN05
__device__ __forceinline__ void mma_ss_cg2(uint32_t d, uint64_t a, uint64_t b,
                                           uint32_t idesc, uint32_t en) {
    asm volatile(
        "{\n\t.reg .pred p;\n\tsetp.ne.u32 p, %4, 0;\n\t"
        "tcgen05.mma.cta_group::2.kind::f16 [%0], %1, %2, %3, "
        "{%5, %5, %5, %5, %5, %5, %5, %5}, p;\n\t}"
        :: "r"(d), "l"(a), "l"(b), "r"(idesc), "r"(en), "r"(0u) : "memory");
}
__device__ __forceinline__ void mma_ts(uint32_t d, uint32_t a, uint64_t b,
                                       uint32_t idesc, uint32_t en) {
    asm volatile(
        "{\n\t.reg .pred p;\n\tsetp.ne.u32 p, %4, 0;\n\t"
        "tcgen05.mma.cta_group::1.kind::f16 [%0], [%1], %2, %3, {%5, %5, %5, %5}, p;\n\t}"
        :: "r"(d), "r"(a), "l"(b), "r"(idesc), "r"(en), "r"(0u) : "memory");
}
#define TC_COMMIT(m) asm volatile( \
    "tcgen05.commit.cta_group::1.mbarrier::arrive::one.shared::cluster.b64 [%0];" :: "r"(m) : "memory")
#define TC_COMMIT_MC2(m) asm volatile( \
    "tcgen05.commit.cta_group::2.mbarrier::arrive::one.shared::cluster.multicast::cluster.b64 [%0], %1;" \
    :: "r"(m), "h"((uint16_t)0x3) : "memory")
#define TC_ALLOC(sm, n)  asm volatile("tcgen05.alloc.cta_group::1.sync.aligned.shared::cta.b32 [%0], %1;" :: "r"(sm), "r"(n) : "memory")
#define TC_DEALLOC(t, n) asm volatile("tcgen05.dealloc.cta_group::1.sync.aligned.b32 %0, %1;" :: "r"(t), "r"(n))
#define TC_ALLOC_CG2(sm, n)  asm volatile("tcgen05.alloc.cta_group::2.sync.aligned.shared::cta.b32 [%0], %1;" :: "r"(sm), "r"(n) : "memory")
#define TC_DEALLOC_CG2(t, n) asm volatile("tcgen05.dealloc.cta_group::2.sync.aligned.b32 %0, %1;" :: "r"(t), "r"(n))
#define TC_RELINQ_CG2() asm volatile("tcgen05.relinquish_alloc_permit.cta_group::2.sync.aligned;")
#define TC_FENCE_AFTER() asm volatile("tcgen05.fence::after_thread_sync;" ::: "memory")
#define TC_FENCE_BEFORE() asm volatile("tcgen05.fence::before_thread_sync;" ::: "memory")
#define TC_WAIT_LD()     asm volatile("tcgen05.wait::ld.sync.aligned;" ::: "memory")
#define TC_WAIT_ST()     asm volatile("tcgen05.wait::st.sync.aligned;" ::: "memory")
#define FENCE_ASYNC()    asm volatile("fence.proxy.async.shared::cta;" ::: "memory")

#define TC_LD_X32(r, a) asm volatile( \
    "tcgen05.ld.sync.aligned.32x32b.x32.b32 " \
    "{%0, %1, %2, %3, %4, %5, %6, %7, %8, %9, %10, %11, %12, %13, %14, %15, " \
    "%16, %17, %18, %19, %20, %21, %22, %23, %24, %25, %26, %27, %28, %29, %30, %31}, [%32];" \
    : "=r"((r)[0]), "=r"((r)[1]), "=r"((r)[2]), "=r"((r)[3]), "=r"((r)[4]), "=r"((r)[5]), \
      "=r"((r)[6]), "=r"((r)[7]), "=r"((r)[8]), "=r"((r)[9]), "=r"((r)[10]), "=r"((r)[11]), \
      "=r"((r)[12]), "=r"((r)[13]), "=r"((r)[14]), "=r"((r)[15]), "=r"((r)[16]), "=r"((r)[17]), \
      "=r"((r)[18]), "=r"((r)[19]), "=r"((r)[20]), "=r"((r)[21]), "=r"((r)[22]), "=r"((r)[23]), \
      "=r"((r)[24]), "=r"((r)[25]), "=r"((r)[26]), "=r"((r)[27]), "=r"((r)[28]), "=r"((r)[29]), \
      "=r"((r)[30]), "=r"((r)[31]) : "r"(a))

#define TC_ST_X32(a, r) asm volatile( \
    "tcgen05.st.sync.aligned.32x32b.x32.b32 [%0], " \
    "{%1, %2, %3, %4, %5, %6, %7, %8, %9, %10, %11, %12, %13, %14, %15, %16, " \
    "%17, %18, %19, %20, %21, %22, %23, %24, %25, %26, %27, %28, %29, %30, %31, %32};" \
    :: "r"(a), \
       "r"((r)[0]), "r"((r)[1]), "r"((r)[2]), "r"((r)[3]), "r"((r)[4]), "r"((r)[5]), \
       "r"((r)[6]), "r"((r)[7]), "r"((r)[8]), "r"((r)[9]), "r"((r)[10]), "r"((r)[11]), \
       "r"((r)[12]), "r"((r)[13]), "r"((r)[14]), "r"((r)[15]), "r"((r)[16]), "r"((r)[17]), \
       "r"((r)[18]), "r"((r)[19]), "r"((r)[20]), "r"((r)[21]), "r"((r)[22]), "r"((r)[23]), \
       "r"((r)[24]), "r"((r)[25]), "r"((r)[26]), "r"((r)[27]), "r"((r)[28]), "r"((r)[29]), \
       "r"((r)[30]), "r"((r)[31]) : "memory")
#endif

// ---- Kernel 0: fused fp32 -> (hi,lo) bf16 ----
__global__ __launch_bounds__(256) void cvt_split2(const float* __restrict__ a,
                                                  const float* __restrict__ w,
                                                  __nv_bfloat16* __restrict__ ah,
                                                  __nv_bfloat16* __restrict__ al,
                                                  __nv_bfloat16* __restrict__ wh,
                                                  __nv_bfloat16* __restrict__ wl,
                                                  int na4, int ntot) {
    int i = blockIdx.x * 256 + threadIdx.x;
    if (i >= ntot) return;
    const float* x; __nv_bfloat16 *hi, *lo; int j;
    if (i < na4) { x = a; hi = ah; lo = al; j = i; }
    else         { x = w; hi = wh; lo = wl; j = i - na4; }
    float4 v = ((const float4*)x)[j];
    __nv_bfloat16 h0 = __float2bfloat16(v.x), h1 = __float2bfloat16(v.y);
    __nv_bfloat16 h2 = __float2bfloat16(v.z), h3 = __float2bfloat16(v.w);
    __nv_bfloat16 l0 = __float2bfloat16(v.x - __bfloat162float(h0));
    __nv_bfloat16 l1 = __float2bfloat16(v.y - __bfloat162float(h1));
    __nv_bfloat16 l2 = __float2bfloat16(v.z - __bfloat162float(h2));
    __nv_bfloat16 l3 = __float2bfloat16(v.w - __bfloat162float(h3));
    ((__nv_bfloat162*)hi)[2 * j] = __nv_bfloat162(h0, h1);
    ((__nv_bfloat162*)hi)[2 * j + 1] = __nv_bfloat162(h2, h3);
    ((__nv_bfloat162*)lo)[2 * j] = __nv_bfloat162(l0, l1);
    ((__nv_bfloat162*)lo)[2 * j + 1] = __nv_bfloat162(l2, l3);
}

// ---- Kernel 1: cg2 GEMM, 256x512 pair tile; epilogue emits fp16 Q/K/V ----
#define GS_AH 0
#define GS_AL 16384
#define GS_W0H 32768
#define GS_W0L 49152
#define GS_W1H 65536
#define GS_W1L 81920
#define G_STG 98304
#define SM_BIAS  196608
#define SM_TMEMP 198656
#define SM_MB    198664
#define SM_KF    198680
#define GEMM_SMEM 198784
#define IDESC_CG2N256 0x10400490u
#define IDESC_BF16 0x8200490u
#define IDESC_FP16 0x8200010u
#define NCH 48

extern __shared__ float smf[];

__global__ __launch_bounds__(256) __cluster_dims__(2, 1, 1)
void qkv_gemm_tc(const float* __restrict__ bias,
                 const float* __restrict__ wq, const float* __restrict__ wk,
                 const float* __restrict__ cs, const float* __restrict__ sn,
                 const int* __restrict__ tsl,
                 const __grid_constant__ CUtensorMap mAh,
                 const __grid_constant__ CUtensorMap mAl,
                 const __grid_constant__ CUtensorMap mWh,
                 const __grid_constant__ CUtensorMap mWl) {
#if HAS_TCGEN05
    char* sm = (char*)smf;
    uint32_t sb = smem_u32(sm);
    int t = threadIdx.x;
    int wid = t >> 5;
    int rank = blockIdx.x & 1;
    int m0 = (blockIdx.x >> 1) * 256 + rank * 128;
    int n0 = blockIdx.y * 512;

    if (wid == 0) TC_ALLOC_CG2(sb + SM_TMEMP, 512);
    if (t == 0) {
        MBAR_INIT(sb + SM_MB + 0, 1);
        MBAR_INIT(sb + SM_MB + 8, 1);
        MBAR_INIT(sb + SM_KF + 0, 1);
        MBAR_INIT(sb + SM_KF + 8, 1);
        FENCE_ASYNC();
        if (rank == 0) {
            MBAR_EXPECT_TX(sb + SM_KF + 0, 196608u);
            MBAR_EXPECT_TX(sb + SM_KF + 8, 196608u);
        }
    }
    ((float*)(sm + SM_BIAS))[t] = bias[n0 + t];
    ((float*)(sm + SM_BIAS))[t + 256] = bias[n0 + t + 256];
    __syncthreads();
    CLUSTER_SYNC();
    uint32_t tmem;
    asm volatile("ld.shared.b32 %0, [%1];" : "=r"(tmem) : "r"(sb + SM_TMEMP));

    if (t == 0) {
#pragma unroll
        for (int c = 0; c < 2; c++) {
            uint32_t stg = sb + c * G_STG, kfb = sb + SM_KF + c * 8;
            int k0 = c * 64;
            TMA_2D_CG2(stg + GS_AH,  &mAh, k0, m0, kfb);
            TMA_2D_CG2(stg + GS_AL,  &mAl, k0, m0, kfb);
            TMA_2D_CG2(stg + GS_W0H, &mWh, k0, n0 + rank * 128, kfb);
            TMA_2D_CG2(stg + GS_W0L, &mWl, k0, n0 + rank * 128, kfb);
            TMA_2D_CG2(stg + GS_W1H, &mWh, k0, n0 + 256 + rank * 128, kfb);
            TMA_2D_CG2(stg + GS_W1L, &mWl, k0, n0 + 256 + rank * 128, kfb);
        }
        const int ca[3] = {0, 0, 1}, cw[3] = {0, 1, 0};
        for (int i = 0; i < NCH; i++) {
            int s = i & 1;
            if (rank == 0) {
                MBAR_WAIT(sb + SM_KF + s * 8, (i >> 1) & 1);
                if (i + 2 < NCH) MBAR_EXPECT_TX(sb + SM_KF + s * 8, 196608u);
                uint32_t stg = sb + s * G_STG;
                uint64_t dA[2]  = {MK_DESC(stg + GS_AH), MK_DESC(stg + GS_AL)};
                uint64_t dW0[2] = {MK_DESC(stg + GS_W0H), MK_DESC(stg + GS_W0L)};
                uint64_t dW1[2] = {MK_DESC(stg + GS_W1H), MK_DESC(stg + GS_W1L)};
#pragma unroll
                for (int c3 = 0; c3 < 3; c3++) {
                    uint64_t b0 = cw[c3] ? dW0[1] : dW0[0];
                    uint64_t b1 = cw[c3] ? dW1[1] : dW1[0];
                    uint64_t aa = dA[ca[c3]];
#pragma unroll
                    for (int ks = 0; ks < 4; ks++) {
                        uint32_t en = (i | c3 | ks) ? 1u : 0u;
                        mma_ss_cg2(tmem,       aa + ks * 2, b0 + ks * 2, IDESC_CG2N256, en);
                        mma_ss_cg2(tmem + 256, aa + ks * 2, b1 + ks * 2, IDESC_CG2N256, en);
                    }
                }
                TC_COMMIT_MC2(sb + SM_MB + s * 8);
            }
            if (i >= 1 && i + 1 < NCH) {
                int s2 = (i + 1) & 1;
                MBAR_WAIT(sb + SM_MB + s2 * 8, ((i - 1) >> 1) & 1);
                uint32_t stg = sb + s2 * G_STG, kfb = sb + SM_KF + s2 * 8;
                int k0 = (i + 1) * 64;
                TMA_2D_CG2(stg + GS_AH,  &mAh, k0, m0, kfb);
                TMA_2D_CG2(stg + GS_AL,  &mAl, k0, m0, kfb);
                TMA_2D_CG2(stg + GS_W0H, &mWh, k0, n0 + rank * 128, kfb);
                TMA_2D_CG2(stg + GS_W0L, &mWl, k0, n0 + rank * 128, kfb);
                TMA_2D_CG2(stg + GS_W1H, &mWh, k0, n0 + 256 + rank * 128, kfb);
                TMA_2D_CG2(stg + GS_W1L, &mWl, k0, n0 + 256 + rank * 128, kfb);
            }
        }
        MBAR_WAIT(sb + SM_MB + 0, 1);
        MBAR_WAIT(sb + SM_MB + 8, 1);
    }
    __syncthreads();
    TC_FENCE_AFTER();

    {
        int r = t & 127;
        int m = m0 + r;
        int b = m / Ss, s2 = m % Ss;
        int sec = n0 / DM;
        int h0 = (n0 % DM) / HD;
        uint32_t tw = tmem + ((uint32_t)(wid & 3) << 21);
        int T = tsl[0];
        bool rope = (s2 >= T);
        int p = s2 - T;
#pragma unroll
        for (int hc2 = 0; hc2 < 2; hc2++) {
            int hc = (t >> 7) + hc2 * 2;
            uint32_t cbase = tw + hc * 128;
            const float* bs = (const float*)(sm + SM_BIAS) + hc * 128;
            size_t obase = ((size_t)(b * Hh + h0 + hc) * Ss + s2) * (size_t)HD;

            if (sec == 2) {
                __half* dv = g_vh + obase;
#pragma unroll
                for (int cb = 0; cb < 4; cb++) {
                    uint32_t rg[32];
                    TC_LD_X32(rg, cbase + cb * 32);
                    TC_WAIT_LD();
                    __half hb[32];
#pragma unroll
                    for (int j = 0; j < 32; j += 2) {
                        float a0 = __uint_as_float(rg[j]) + bs[cb * 32 + j];
                        float a1 = __uint_as_float(rg[j + 1]) + bs[cb * 32 + j + 1];
                        *(__half2*)(hb + j) = __float22half2_rn(make_float2(a0, a1));
                    }
#pragma unroll
                    for (int q4 = 0; q4 < 4; q4++)
                        *(uint4*)(dv + cb * 32 + q4 * 8) = *(uint4*)(hb + q4 * 8);
                }
            } else {
                const float* wn = (sec == 0) ? wq : wk;
                float ssq = 0.0f;
#pragma unroll
                for (int cb = 0; cb < 4; cb++) {
                    uint32_t rg[32];
                    TC_LD_X32(rg, cbase + cb * 32);
                    TC_WAIT_LD();
#pragma unroll
                    for (int j = 0; j < 32; j++) {
                        float a = __uint_as_float(rg[j]) + bs[cb * 32 + j];
                        ssq += a * a;
                    }
                }
                float rms = rsqrtf(ssq * (1.0f / 128.0f) + 1e-6f);
                // qscale = (1/sqrt(128)) * log2(e): attention uses exp2
                float qscale = (sec == 0) ? 0.12752050778924437f : 1.0f;
                __half* dq = ((sec == 0) ? g_qf : g_kf) + obase;
#pragma unroll
                for (int cb = 0; cb < 4; cb++) {
                    uint32_t rg[32];
                    TC_LD_X32(rg, cbase + cb * 32);
                    TC_WAIT_LD();
                    float y[32];
#pragma unroll
                    for (int j = 0; j < 32; j++)
                        y[j] = (__uint_as_float(rg[j]) + bs[cb * 32 + j]) * rms * wn[cb * 32 + j];
                    if (rope) {
#pragma unroll
                        for (int jj = 0; jj < 16; jj++) {
                            float c = cs[p * 64 + cb * 16 + jj], sv = sn[p * 64 + cb * 16 + jj];
                            float x1 = y[2 * jj], x2 = y[2 * jj + 1];
                            y[2 * jj] = x1 * c - x2 * sv;
                            y[2 * jj + 1] = x2 * c + x1 * sv;
                        }
                    }
                    __half hb[32];
#pragma unroll
                    for (int j = 0; j < 32; j += 2)
                        *(__half2*)(hb + j) = __float22half2_rn(
                            make_float2(y[j] * qscale, y[j + 1] * qscale));
#pragma unroll
                    for (int q4 = 0; q4 < 4; q4++)
                        *(uint4*)(dq + cb * 32 + q4 * 8) = *(uint4*)(hb + q4 * 8);
                }
            }
        }
    }
    __syncthreads();
    if (wid == 0) { TC_RELINQ_CG2(); TC_DEALLOC_CG2(tmem, 512); }
    CLUSTER_SYNC();
#endif
}

// ---- Kernel 2b: V transpose ----
__global__ __launch_bounds__(256) void v_transpose() {
    __shared__ __half ts[128 * 129];
    int t = threadIdx.x;
    int s0 = blockIdx.x * 128;
    int bh = blockIdx.y;
    const __half* src = g_vh + ((size_t)bh * Ss + s0) * HD;
#pragma unroll
    for (int i = 0; i < 8; i++) {
        int idx = t + i * 256;
        int s = idx >> 4, c8 = idx & 15;
        uint4 v = *(const uint4*)(src + s * HD + c8 * 8);
        __half tmp[8];
        *(uint4*)tmp = v;
#pragma unroll
        for (int j = 0; j < 8; j++) ts[s * 129 + c8 * 8 + j] = tmp[j];
    }
    __syncthreads();
    __half* dst = g_vt + (size_t)bh * HD * Ss;
#pragma unroll
    for (int i = 0; i < 8; i++) {
        int idx = t + i * 256;
        int d = idx >> 4, s8 = idx & 15;
        __half o[8];
#pragma unroll
        for (int j = 0; j < 8; j++) o[j] = ts[(s8 * 8 + j) * 129 + d];
        *(uint4*)(dst + (size_t)d * Ss + s0 + s8 * 8) = *(uint4*)o;
    }
}

// ---- Kernel 3: attention — R15 loop, fp16 single-operand QK ----
#define A_STG 65536
#define AS_K  0
#define AS_V  32768
#define A_SMAX 131072
#define A_SSUM 132096
#define A_PTR  133120
#define A_MBS  133128
#define A_MBO  133136
#define A_KF   133144
#define ATT_SMEM 133248
#define NT 18
#define TO_O  0
#define TO_S  128
#define TO_P  256
#define TO_Q  320

__device__ __forceinline__ uint32_t dstep(int ks) {
    return (uint32_t)((ks >> 2) * 1024 + (ks & 3) * 2);
}

__global__ __launch_bounds__(256, 1) void attn(
        float* __restrict__ out,
        const __grid_constant__ CUtensorMap mKf,
        const __grid_constant__ CUtensorMap mVt) {
#if HAS_TCGEN05
    char* sm = (char*)smf;
    uint32_t sb = smem_u32(sm);
    int t = threadIdx.x;
    int wid = t >> 5;
    int row = t & 127;
    int half = t >> 7;
    int q0 = blockIdx.x * 128;
    int h = blockIdx.y, b = blockIdx.z;
    int bh = b * Hh + h;

    if (wid == 0) TC_ALLOC(sb + A_PTR, 512);
    if (t == 0) {
        MBAR_INIT(sb + A_MBS, 1);
        MBAR_INIT(sb + A_MBO, 1);
        MBAR_INIT(sb + A_KF + 0, 1);
        MBAR_INIT(sb + A_KF + 8, 1);
        FENCE_ASYNC();
        MBAR_EXPECT_TX(sb + A_KF, 65536u);
        TMA_3D(sb + AS_K,         &mKf, 0,  0, bh, sb + A_KF);
        TMA_3D(sb + AS_K + 16384, &mKf, 64, 0, bh, sb + A_KF);
        TMA_3D(sb + AS_V,         &mVt, 0,  0, bh, sb + A_KF);
        TMA_3D(sb + AS_V + 16384, &mVt, 64, 0, bh, sb + A_KF);
    }
    __syncthreads();
    uint32_t tmem;
    asm volatile("ld.shared.b32 %0, [%1];" : "=r"(tmem) : "r"(sb + A_PTR));
    uint32_t tw = tmem + ((uint32_t)(wid & 3) << 21);

    // Q prologue: fp16 row -> 64 TMEM cols (t<128 cols 0-31, t>=128 cols 32-63)
    {
        const uint4* qsrc = (const uint4*)(g_qf + ((size_t)bh * Ss + q0 + row) * HD);
        uint32_t rg[32];
#pragma unroll
        for (int j = 0; j < 8; j++) ((uint4*)rg)[j] = qsrc[half * 8 + j];
        TC_ST_X32(tw + TO_Q + half * 32, rg);
        TC_WAIT_ST();
    }
    TC_FENCE_BEFORE();
    __syncthreads();

    float m_ref = -1e30f, l = 0.0f;

    for (int iter = 0; iter < NT; iter++) {
        int s = iter & 1;
        uint32_t stg = sb + s * A_STG;

        // S-MMA: single fp16 term  S = Q * K
        if (t == 0) {
            TC_FENCE_AFTER();
            MBAR_WAIT(sb + A_KF + s * 8, (iter >> 1) & 1);
            uint64_t dK = MK_DESC(stg + AS_K);
#pragma unroll
            for (int ks = 0; ks < 8; ks++)
                mma_ts(tmem + TO_S, tmem + TO_Q + ks * 8, dK + dstep(ks), IDESC_FP16, ks > 0);
            TC_COMMIT(sb + A_MBS);
        }

        if (iter > 0) MBAR_WAIT(sb + A_MBO, (iter - 1) & 1);

        if (t == 0 && iter + 1 < NT) {
            int s2 = (iter + 1) & 1;
            uint32_t st2 = sb + s2 * A_STG;
            int kt = (iter + 1) * 128;
            MBAR_EXPECT_TX(sb + A_KF + s2 * 8, 65536u);
            TMA_3D(st2 + AS_K,         &mKf, 0,  kt, bh, sb + A_KF + s2 * 8);
            TMA_3D(st2 + AS_K + 16384, &mKf, 64, kt, bh, sb + A_KF + s2 * 8);
            TMA_3D(st2 + AS_V,         &mVt, kt,      0, bh, sb + A_KF + s2 * 8);
            TMA_3D(st2 + AS_V + 16384, &mVt, kt + 64, 0, bh, sb + A_KF + s2 * 8);
        }

        // softmax in exp2 domain
        {
            MBAR_WAIT(sb + A_MBS, iter & 1);
            TC_FENCE_AFTER();
            float sc[64];
            uint32_t* scu = (uint32_t*)sc;
            uint32_t scol = tw + TO_S + half * 64;
            TC_LD_X32(scu + 0,  scol + 0);
            TC_LD_X32(scu + 32, scol + 32);
            TC_WAIT_LD();
            float pmax = sc[0];
#pragma unroll
            for (int c = 1; c < 64; c++) pmax = fmaxf(pmax, sc[c]);
            ((float*)(sm + A_SMAX))[t] = pmax;
            __syncthreads();
            float tmax = fmaxf(pmax, ((float*)(sm + A_SMAX))[t ^ 128]);
            bool need = tmax > m_ref + 6.0f;
            float alpha = 1.0f;
            if (need) { alpha = exp2f(m_ref - tmax); m_ref = tmax; }
            float psum = 0.0f;
            uint32_t pr[32];
#pragma unroll
            for (int c = 0; c < 32; c++) {
                float p0 = exp2f(sc[2 * c] - m_ref);
                float p1 = exp2f(sc[2 * c + 1] - m_ref);
                psum += p0 + p1;
                pr[c] = h2_as_u32(__float22half2_rn(make_float2(p0, p1)));
            }
            ((float*)(sm + A_SSUM))[t] = psum;
            TC_ST_X32(tw + TO_P + half * 32, pr);
            if (iter > 0 && __any_sync(0xffffffffu, need)) {
#pragma unroll
                for (int cb = 0; cb < 2; cb++) {
                    uint32_t og[32];
                    TC_LD_X32(og, tw + TO_O + half * 64 + cb * 32);
                    TC_WAIT_LD();
                    float* of = (float*)og;
#pragma unroll
                    for (int j = 0; j < 32; j++) of[j] *= alpha;
                    TC_ST_X32(tw + TO_O + half * 64 + cb * 32, og);
                }
            }
            TC_WAIT_ST();
            TC_FENCE_BEFORE();
            __syncthreads();
            l = l * alpha + psum + ((float*)(sm + A_SSUM))[t ^ 128];
        }

        if (t == 0) {
            TC_FENCE_AFTER();
            uint64_t dV = MK_DESC(stg + AS_V);
#pragma unroll
            for (int ks = 0; ks < 8; ks++)
                mma_ts(tmem + TO_O, tmem + TO_P + ks * 8, dV + dstep(ks), IDESC_FP16,
                       (iter > 0) || (ks > 0));
            TC_COMMIT(sb + A_MBO);
        }
    }

    MBAR_WAIT(sb + A_MBO, (NT - 1) & 1);
    TC_FENCE_AFTER();
    {
        float inv = 1.0f / l;
        float* dst = out + ((size_t)b * Ss + q0 + row) * DM + h * HD + half * 64;
#pragma unroll
        for (int cb = 0; cb < 2; cb++) {
            uint32_t og[32];
            TC_LD_X32(og, tw + TO_O + half * 64 + cb * 32);
            TC_WAIT_LD();
            float* of = (float*)og;
#pragma unroll
            for (int j = 0; j < 32; j += 4) {
                float4 o = make_float4(of[j] * inv, of[j + 1] * inv,
                                       of[j + 2] * inv, of[j + 3] * inv);
                *(float4*)(dst + cb * 32 + j) = o;
            }
        }
    }
    __syncthreads();
    if (wid == 0) TC_DEALLOC(tmem, 512);
#endif
}

// ---- Host ----
typedef CUresult (*PFN_encodeTiled)(CUtensorMap*, CUtensorMapDataType, cuuint32_t,
                                    void*, const cuuint64_t*, const cuuint64_t*,
                                    const cuuint32_t*, const cuuint32_t*,
                                    CUtensorMapInterleave, CUtensorMapSwizzle,
                                    CUtensorMapL2promotion, CUtensorMapFloatOOBfill);
static PFN_encodeTiled get_encoder() {
    static PFN_encodeTiled fn = nullptr;
    if (!fn) {
        cudaDriverEntryPointQueryResult qr;
        cudaGetDriverEntryPointByVersion("cuTensorMapEncodeTiled", (void**)&fn,
                                         12000, cudaEnableDefault, &qr);
    }
    return fn;
}
static void enc(CUtensorMap* m, void* base, int nd, uint64_t d0, uint64_t d1, uint64_t d2,
                uint32_t b0, uint32_t b1, CUtensorMapDataType dt) {
    cuuint64_t dims[3] = {d0, d1, d2};
    cuuint64_t strides[2] = {d0 * 2, d0 * d1 * 2};
    cuuint32_t box[3] = {b0, b1, 1};
    cuuint32_t es[3] = {1, 1, 1};
    get_encoder()(m, dt, nd, base, dims, strides, box, es,
                  CU_TENSOR_MAP_INTERLEAVE_NONE, CU_TENSOR_MAP_SWIZZLE_128B,
                  CU_TENSOR_MAP_L2_PROMOTION_L2_128B, CU_TENSOR_MAP_FLOAT_OOB_FILL_NONE);
}

extern "C" void kernel_launch(void* const* d_in, const int* in_sizes, int n_in,
                              void* d_out, int out_size) {
    const float* hs  = (const float*)d_in[0];
    const float* w   = (const float*)d_in[1];
    const float* bqv = (const float*)d_in[2];
    const float* wqn = (const float*)d_in[3];
    const float* wkn = (const float*)d_in[4];
    const float* cs  = (const float*)d_in[5];
    const float* sn  = (const float*)d_in[6];
    const int*   tsl = (const int*)d_in[7];
    float* out = (float*)d_out;

    __nv_bfloat16 *ah, *al, *wh, *wl;
    __half *kf, *vt;
    cudaGetSymbolAddress((void**)&ah, g_Ah);
    cudaGetSymbolAddress((void**)&al, g_Al);
    cudaGetSymbolAddress((void**)&wh, g_Wh);
    cudaGetSymbolAddress((void**)&wl, g_Wl);
    cudaGetSymbolAddress((void**)&kf, g_kf);
    cudaGetSymbolAddress((void**)&vt, g_vt);

    CUtensorMap mAh, mAl, mWh, mWl, mKf, mVt;
    enc(&mAh, ah, 2, KD, MR, 1, 64, 128, CU_TENSOR_MAP_DATA_TYPE_BFLOAT16);
    enc(&mAl, al, 2, KD, MR, 1, 64, 128, CU_TENSOR_MAP_DATA_TYPE_BFLOAT16);
    enc(&mWh, wh, 2, KD, N3, 1, 64, 128, CU_TENSOR_MAP_DATA_TYPE_BFLOAT16);
    enc(&mWl, wl, 2, KD, N3, 1, 64, 128, CU_TENSOR_MAP_DATA_TYPE_BFLOAT16);
    enc(&mKf, kf, 3, HD, Ss, Bb * Hh, 64, 128, CU_TENSOR_MAP_DATA_TYPE_FLOAT16);
    enc(&mVt, vt, 3, Ss, HD, Bb * Hh, 64, 128, CU_TENSOR_MAP_DATA_TYPE_FLOAT16);

    int na4 = MR * KD / 4;
    int nw4 = N3 * KD / 4;
    int ntot = na4 + nw4;
    cvt_split2<<<(ntot + 255) / 256, 256>>>(hs, w, ah, al, wh, wl, na4, ntot);

    cudaFuncSetAttribute(qkv_gemm_tc, cudaFuncAttributeMaxDynamicSharedMemorySize, GEMM_SMEM);
    qkv_gemm_tc<<<dim3(MR / 128, N3 / 512), 256, GEMM_SMEM>>>(bqv, wqn, wkn, cs, sn, tsl,
                                                              mAh, mAl, mWh, mWl);

    v_transpose<<<dim3(Ss / 128, Bb * Hh), 256>>>();

    cudaFuncSetAttribute(attn, cudaFuncAttributeMaxDynamicSharedMemorySize, ATT_SMEM);
    attn<<<dim3(Ss / 128, Hh, Bb), 256, ATT_SMEM>>>(out, mKf, mVt);
}